// round 11
// baseline (speedup 1.0000x reference)
#include <cuda_runtime.h>
#include <cuda_fp16.h>
#include <math.h>
#include <stdint.h>

#define TOK   100352          // B*H*W tokens
#define CC    192
#define NHEAD 6
#define HDIM  32
#define NWIN  2048            // B * 64 windows
#define HIDN  768

// Scratch (allocation-free rule: __device__ globals).
__device__ __half g_xn [TOK * CC];        // LN1 out, A-frag image
__device__ __half g_qkv[TOK * 3 * CC];    // qkv, linear half
__device__ __half g_att[TOK * CC];        // attn out, A-frag image
__device__ float  g_xr [TOK * CC];        // residual branch, fp32 linear
__device__ __half g_h  [TOK * CC];        // LN2 out, A-frag image
__device__ __half g_h1 [TOK * HIDN];      // fc1+gelu out, A-frag image
__device__ __half g_w  [442368];          // B-frag images (qkv|proj|fc1|fc2)
__device__ float  g_msk[64 * 49 * 56];    // padded mask [win][r][j56], -1e9 pad

#define OFF_QKVW  0
#define OFF_PROJW 110592
#define OFF_FC1W  147456
#define OFF_FC2W  294912

__device__ __forceinline__ int win_row_to_token(int row) {
    int win = row / 49, n = row % 49;
    int b   = win >> 6, wij = win & 63;
    int wi  = wij >> 3, wj  = wij & 7;
    int hh  = wi * 7 + n / 7;
    int ww  = wj * 7 + n % 7;
    int h = hh + 3; if (h >= 56) h -= 56;
    int w = ww + 3; if (w >= 56) w -= 56;
    return b * 3136 + h * 56 + w;
}

// A-fragment image (half) index for (row, col) of an [*, K] activation (m16n8k16).
__device__ __forceinline__ size_t aimg_idx(int row, int col, int K) {
    int nk  = K >> 5;
    int mb  = row >> 8, m = row & 255;
    int ch  = col >> 5, kin = col & 31;
    int m16 = m >> 4, rr = m & 15;
    int gid = rr & 7, hr = rr >> 3;
    int ks  = kin >> 4, kk = kin & 15;
    int hi  = kk >> 3, q = (kk & 7) >> 1, e = kk & 1;
    int lane = gid * 4 + q;
    int reg  = hi * 2 + hr;
    return ((size_t)mb * nk + ch) * 8192
         + (size_t)((m16 * 2 + ks) * 256 + lane * 8 + reg * 2 + e);
}

// B-fragment image (half) index for weight element (k, n), K the k-dim.
__device__ __forceinline__ size_t bimg_idx(int k, int n, int K) {
    int nk = K >> 5;
    int bx = n >> 6, n64 = n & 63;
    int ch = k >> 5, kin = k & 31;
    int ks = kin >> 4, kk = kin & 15;
    int hi = kk >> 3, q = (kk & 7) >> 1, e = kk & 1;
    int sg = n64 >> 4, ntp = (n64 >> 3) & 1, g = n64 & 7;
    int lane = g * 4 + q;
    return ((size_t)bx * nk + ch) * 2048
         + (size_t)((ks * 4 + sg) * 256 + lane * 8 + ntp * 4 + hi * 2 + e);
}

__device__ __forceinline__ void mma16(float* c, uint4 a, uint32_t b0, uint32_t b1) {
    asm volatile(
        "mma.sync.aligned.m16n8k16.row.col.f32.f16.f16.f32 "
        "{%0,%1,%2,%3},{%4,%5,%6,%7},{%8,%9},{%0,%1,%2,%3};"
        : "+f"(c[0]), "+f"(c[1]), "+f"(c[2]), "+f"(c[3])
        : "r"(a.x), "r"(a.y), "r"(a.z), "r"(a.w), "r"(b0), "r"(b1));
}

// Combined prep: 4 weight B-frag images + padded mask, one launch.
__global__ void prep_all(const float* __restrict__ qkv_w, const float* __restrict__ proj_w,
                         const float* __restrict__ fc1w, const float* __restrict__ fc2w,
                         const float* __restrict__ amask,
                         __half* __restrict__ w, float* __restrict__ msk)
{
    int i = blockIdx.x * 256 + threadIdx.x;
    if (i < 110592) {
        int k = i / 576, n = i % 576;
        w[OFF_QKVW + bimg_idx(k, n, 192)] = __float2half_rn(qkv_w[i]);
    } else if (i < 147456) {
        int j = i - 110592, k = j / 192, n = j % 192;
        w[OFF_PROJW + bimg_idx(k, n, 192)] = __float2half_rn(proj_w[j]);
    } else if (i < 294912) {
        int j = i - 147456, k = j / 768, n = j % 768;
        w[OFF_FC1W + bimg_idx(k, n, 192)] = __float2half_rn(fc1w[j]);
    } else if (i < 442368) {
        int j = i - 294912, k = j / 192, n = j % 192;
        w[OFF_FC2W + bimg_idx(k, n, 768)] = __float2half_rn(fc2w[j]);
    } else if (i < 442368 + 64 * 49 * 56) {
        int j = i - 442368;
        int win = j / 2744, rj = j % 2744, r = rj / 56, jj = rj % 56;
        msk[j] = (jj < 49) ? amask[win * 2401 + r * 49 + jj] : -1e9f;
    }
}

// LayerNorm over C=192, one warp per row; writes half A-frag image.
__global__ void ln_kernel(const float* __restrict__ x, const float* __restrict__ g,
                          const float* __restrict__ bta, __half* __restrict__ out,
                          int permute)
{
    int row  = blockIdx.x * 8 + threadIdx.y;
    int lane = threadIdx.x;
    int src  = permute ? win_row_to_token(row) : row;
    const float* xp = x + (size_t)src * CC;
    float2 v[3];
    float s = 0.f, s2 = 0.f;
#pragma unroll
    for (int i = 0; i < 3; i++) {
        v[i] = *(const float2*)&xp[i * 64 + lane * 2];
        s += v[i].x + v[i].y;
        s2 += v[i].x * v[i].x + v[i].y * v[i].y;
    }
#pragma unroll
    for (int o = 16; o; o >>= 1) {
        s  += __shfl_xor_sync(0xffffffffu, s, o);
        s2 += __shfl_xor_sync(0xffffffffu, s2, o);
    }
    float mu  = s * (1.f / 192.f);
    float var = s2 * (1.f / 192.f) - mu * mu;
    float inv = rsqrtf(var + 1e-5f);
#pragma unroll
    for (int i = 0; i < 3; i++) {
        int c = i * 64 + lane * 2;
        float2 gg = *(const float2*)&g[c];
        float2 bb = *(const float2*)&bta[c];
        float o0 = (v[i].x - mu) * inv * gg.x + bb.x;
        float o1 = (v[i].y - mu) * inv * gg.y + bb.y;
        *(__half2*)&out[aimg_idx(row, c, 192)] = __floats2half2_rn(o0, o1);
    }
}

// FP16 mma.sync GEMM: CTA 128x192, 6 warps (2m x 3n), warp tile 64x64.
// A/B fp16 fragment images, cp.async double buffered.
// EPI: 0 bias -> half linear; 1 bias+permuted write -> fp32 linear;
//      2 bias+GELU -> half A-image (K'=768); 3 bias+residual -> fp32 linear.
template<int EPI>
__global__ void __launch_bounds__(192, 2)
tgemm(const __half* __restrict__ Aimg, const __half* __restrict__ Bimg,
      const float* __restrict__ bias, void* __restrict__ CoutV,
      int Nn, int K, const float* __restrict__ resid)
{
    extern __shared__ __half dsh[];
    __half* Asm = dsh;                // [2][4096] halves = 16KB
    __half* Bsm = dsh + 2 * 4096;     // [2][3*2048] halves = 24KB

    const int tid  = threadIdx.x;
    const int warp = tid >> 5, lane = tid & 31;
    const int gid = lane >> 2, qid = lane & 3;
    const int wm = warp / 3, wn = warp % 3;
    const int bm = blockIdx.y * 128;
    const int bn0 = blockIdx.x * 192;
    const int nk = K >> 5;

    float acc[4][8][4] = {};

    const uint32_t asmb = (uint32_t)__cvta_generic_to_shared(Asm);
    const uint32_t bsmb = asmb + 16384;
    // A chunk base: 256-row image blocks; this CTA uses half of one block.
    const __half* Ab = Aimg + (size_t)(bm >> 8) * nk * 8192 + ((bm >> 7) & 1) * 4096;
    const int bx0 = blockIdx.x * 3;

    auto issue = [&](int c) {
        int st = c & 1;
        const uint4* as = (const uint4*)(Ab + (size_t)c * 8192);
        uint32_t ad = asmb + (uint32_t)(st * 8192);
#pragma unroll
        for (int p = 0; p < 3; p++) {
            int idx = tid + p * 192;
            if (p < 2 || idx < 512)
                asm volatile("cp.async.cg.shared.global [%0], [%1], 16;"
                             :: "r"(ad + idx * 16), "l"(as + idx));
        }
        uint32_t bd = bsmb + (uint32_t)(st * 12288);
#pragma unroll
        for (int p = 0; p < 4; p++) {
            int idx = tid + p * 192;          // 0..767 (3 x-blocks x 256 uint4)
            int xb = idx >> 8, off = idx & 255;
            const uint4* bs = (const uint4*)(Bimg + ((size_t)(bx0 + xb) * nk + c) * 2048) + off;
            asm volatile("cp.async.cg.shared.global [%0], [%1], 16;"
                         :: "r"(bd + idx * 16), "l"(bs));
        }
        asm volatile("cp.async.commit_group;" ::: "memory");
    };

    issue(0);
    for (int c = 0; c < nk; c++) {
        if (c + 1 < nk) {
            issue(c + 1);
            asm volatile("cp.async.wait_group 1;" ::: "memory");
        } else {
            asm volatile("cp.async.wait_group 0;" ::: "memory");
        }
        __syncthreads();

        const __half* ab = Asm + (c & 1) * 4096;
        const __half* bb = Bsm + (c & 1) * 6144 + wn * 2048;
#pragma unroll
        for (int ks = 0; ks < 2; ks++) {
            uint4 fa[4];
#pragma unroll
            for (int mt = 0; mt < 4; mt++)
                fa[mt] = *(const uint4*)&ab[(((wm * 4 + mt) * 2) + ks) * 256 + lane * 8];
#pragma unroll
            for (int s = 0; s < 4; s++) {
                uint4 fb = *(const uint4*)&bb[(ks * 4 + s) * 256 + lane * 8];
#pragma unroll
                for (int mt = 0; mt < 4; mt++) {
                    mma16(acc[mt][s * 2],     fa[mt], fb.x, fb.y);
                    mma16(acc[mt][s * 2 + 1], fa[mt], fb.z, fb.w);
                }
            }
        }
        __syncthreads();
    }

    // Epilogue. acc frag: c0:(g,2q) c1:(g,2q+1) c2:(g+8,2q) c3:(g+8,2q+1)
#pragma unroll
    for (int mt = 0; mt < 4; mt++) {
#pragma unroll
        for (int hf = 0; hf < 2; hf++) {
            int row  = bm + wm * 64 + mt * 16 + gid + hf * 8;
            int orow = (EPI == 1) ? win_row_to_token(row) : row;
#pragma unroll
            for (int nt = 0; nt < 8; nt++) {
                int col = bn0 + wn * 64 + nt * 8 + qid * 2;
                float v0 = acc[mt][nt][hf * 2 + 0] + bias[col];
                float v1 = acc[mt][nt][hf * 2 + 1] + bias[col + 1];
                if (EPI == 0) {
                    __half* O = (__half*)CoutV;
                    *(__half2*)&O[(size_t)row * Nn + col] = __floats2half2_rn(v0, v1);
                } else if (EPI == 1) {
                    float* O = (float*)CoutV;
                    *(float2*)&O[(size_t)orow * Nn + col] = make_float2(v0, v1);
                } else if (EPI == 2) {
                    v0 = 0.5f * v0 * (1.f + erff(v0 * 0.70710678118654752f));
                    v1 = 0.5f * v1 * (1.f + erff(v1 * 0.70710678118654752f));
                    __half* O = (__half*)CoutV;
                    *(__half2*)&O[aimg_idx(row, col, 768)] = __floats2half2_rn(v0, v1);
                } else {
                    float* O = (float*)CoutV;
                    float r0 = resid[(size_t)row * CC + col];
                    float r1 = resid[(size_t)row * CC + col + 1];
                    *(float2*)&O[(size_t)row * Nn + col] = make_float2(v0 + r0, v1 + r1);
                }
            }
        }
    }
}

// FP16 tensor-core attention: one CTA per (window, head), 4 warps.
__global__ void __launch_bounds__(128)
attn_kernel(const __half* __restrict__ qkv, const float* __restrict__ mask2,
            __half* __restrict__ out)
{
    int win  = blockIdx.x / NHEAD;
    int head = blockIdx.x % NHEAD;
    __shared__ __half qa[2048];        // Q A-frag image: 4 m16 x 2 ks x 256
    __shared__ __half kt[56 * 40];     // K [j][d], stride 40
    __shared__ __half vt[32 * 72];     // V^T [d][j], stride 72, j padded to 64
    __shared__ __half pim[4096];       // P A-frag image: 4 m16 x 4 ks x 256

    const int tid = threadIdx.x;
    const int warp = tid >> 5, lane = tid & 31;
    const int gid = lane >> 2, qid = lane & 3;
    const float scale = 0.17677669529663687f;

    {
        uint32_t* z;
        z = (uint32_t*)qa;  for (int t = tid; t < 1024; t += 128) z[t] = 0;
        z = (uint32_t*)kt;  for (int t = tid; t < 1120; t += 128) z[t] = 0;
        z = (uint32_t*)vt;  for (int t = tid; t < 1152; t += 128) z[t] = 0;
        z = (uint32_t*)pim; for (int t = tid; t < 2048; t += 128) z[t] = 0;
    }
    __syncthreads();

    const __half* base = qkv + (size_t)win * 49 * 576;
    for (int t = tid; t < 49 * 16; t += 128) {
        int r = t >> 4, c = (t & 15) * 2;
        __half2 qh = *(const __half2*)&base[r * 576 +       head * 32 + c];
        __half2 kh = *(const __half2*)&base[r * 576 + 192 + head * 32 + c];
        __half2 vh = *(const __half2*)&base[r * 576 + 384 + head * 32 + c];
        float2 qf = __half22float2(qh);
        int m16 = r >> 4, rr = r & 15;
        int ks = c >> 4, kk = c & 15;
        int ln = (rr & 7) * 4 + ((kk & 7) >> 1);
        int reg = (kk >> 3) * 2 + (rr >> 3);
        *(__half2*)&qa[(m16 * 2 + ks) * 256 + ln * 8 + reg * 2] =
            __floats2half2_rn(qf.x * scale, qf.y * scale);
        *(__half2*)&kt[r * 40 + c] = kh;
        vt[c * 72 + r]       = vh.x;
        vt[(c + 1) * 72 + r] = vh.y;
    }
    __syncthreads();

    float sacc[7][4] = {};
#pragma unroll
    for (int ks = 0; ks < 2; ks++) {
        uint4 fa = *(const uint4*)&qa[(warp * 2 + ks) * 256 + lane * 8];
#pragma unroll
        for (int nt = 0; nt < 7; nt++) {
            uint32_t b0 = *(const uint32_t*)&kt[(nt * 8 + gid) * 40 + ks * 16 + qid * 2];
            uint32_t b1 = *(const uint32_t*)&kt[(nt * 8 + gid) * 40 + ks * 16 + 8 + qid * 2];
            mma16(sacc[nt], fa, b0, b1);
        }
    }

    const float* msk = mask2 + (size_t)(win & 63) * 2744;
#pragma unroll
    for (int hf = 0; hf < 2; hf++) {
        int r = warp * 16 + hf * 8 + gid;
        bool ok = (r < 49);
        float v[14];
#pragma unroll
        for (int nt = 0; nt < 7; nt++) {
            float2 mk = ok ? *(const float2*)&msk[r * 56 + nt * 8 + qid * 2]
                           : make_float2(-1e9f, -1e9f);
            v[nt * 2]     = sacc[nt][hf * 2]     + mk.x;
            v[nt * 2 + 1] = sacc[nt][hf * 2 + 1] + mk.y;
        }
        float m = v[0];
#pragma unroll
        for (int i = 1; i < 14; i++) m = fmaxf(m, v[i]);
        m = fmaxf(m, __shfl_xor_sync(0xffffffffu, m, 1));
        m = fmaxf(m, __shfl_xor_sync(0xffffffffu, m, 2));
        float s = 0.f;
#pragma unroll
        for (int i = 0; i < 14; i++) { v[i] = __expf(v[i] - m); s += v[i]; }
        s += __shfl_xor_sync(0xffffffffu, s, 1);
        s += __shfl_xor_sync(0xffffffffu, s, 2);
        float inv = 1.f / s;
#pragma unroll
        for (int nt = 0; nt < 7; nt++) {
            *(__half2*)&pim[(warp * 4 + (nt >> 1)) * 256 + lane * 8 + (nt & 1) * 4 + hf * 2] =
                __floats2half2_rn(v[nt * 2] * inv, v[nt * 2 + 1] * inv);
        }
    }

    float oacc[4][4] = {};
#pragma unroll
    for (int ks = 0; ks < 4; ks++) {
        uint4 fa = *(const uint4*)&pim[(warp * 4 + ks) * 256 + lane * 8];
#pragma unroll
        for (int nt = 0; nt < 4; nt++) {
            uint32_t b0 = *(const uint32_t*)&vt[(nt * 8 + gid) * 72 + ks * 16 + qid * 2];
            uint32_t b1 = *(const uint32_t*)&vt[(nt * 8 + gid) * 72 + ks * 16 + 8 + qid * 2];
            mma16(oacc[nt], fa, b0, b1);
        }
    }

    int i0 = warp * 16 + gid, i1 = warp * 16 + 8 + gid;
#pragma unroll
    for (int nt = 0; nt < 4; nt++) {
        int d = head * 32 + nt * 8 + qid * 2;
        if (i0 < 49) {
            int r0 = win * 49 + i0;
            *(__half2*)&out[aimg_idx(r0, d, 192)] =
                __floats2half2_rn(oacc[nt][0], oacc[nt][1]);
        }
        if (i1 < 49) {
            int r1 = win * 49 + i1;
            *(__half2*)&out[aimg_idx(r1, d, 192)] =
                __floats2half2_rn(oacc[nt][2], oacc[nt][3]);
        }
    }
}

extern "C" void kernel_launch(void* const* d_in, const int* in_sizes, int n_in,
                              void* d_out, int out_size)
{
    const float* x      = (const float*)d_in[0];
    const float* qkv_w  = (const float*)d_in[1];
    const float* qkv_b  = (const float*)d_in[2];
    const float* proj_w = (const float*)d_in[3];
    const float* proj_b = (const float*)d_in[4];
    const float* n1g    = (const float*)d_in[5];
    const float* n1b    = (const float*)d_in[6];
    const float* n2g    = (const float*)d_in[7];
    const float* n2b    = (const float*)d_in[8];
    const float* fc1w   = (const float*)d_in[9];
    const float* fc1b   = (const float*)d_in[10];
    const float* fc2w   = (const float*)d_in[11];
    const float* fc2b   = (const float*)d_in[12];
    const float* amask  = (const float*)d_in[13];
    float* out = (float*)d_out;

    __half *xn, *qkv, *att, *h, *h1, *w;
    float *xr, *msk;
    cudaGetSymbolAddress((void**)&xn,  g_xn);
    cudaGetSymbolAddress((void**)&qkv, g_qkv);
    cudaGetSymbolAddress((void**)&att, g_att);
    cudaGetSymbolAddress((void**)&xr,  g_xr);
    cudaGetSymbolAddress((void**)&h,   g_h);
    cudaGetSymbolAddress((void**)&h1,  g_h1);
    cudaGetSymbolAddress((void**)&w,   g_w);
    cudaGetSymbolAddress((void**)&msk, g_msk);

    const int SMEM_GEMM = 40960;   // 16KB A + 24KB B
    cudaFuncSetAttribute(tgemm<0>, cudaFuncAttributeMaxDynamicSharedMemorySize, SMEM_GEMM);
    cudaFuncSetAttribute(tgemm<1>, cudaFuncAttributeMaxDynamicSharedMemorySize, SMEM_GEMM);
    cudaFuncSetAttribute(tgemm<2>, cudaFuncAttributeMaxDynamicSharedMemorySize, SMEM_GEMM);
    cudaFuncSetAttribute(tgemm<3>, cudaFuncAttributeMaxDynamicSharedMemorySize, SMEM_GEMM);

    // 0) build B fragment images + padded mask (one launch)
    prep_all<<<(442368 + 64 * 49 * 56 + 255) / 256, 256>>>(
        qkv_w, proj_w, fc1w, fc2w, amask, w, msk);

    dim3 lnb(32, 8);
    // 1) shift + window partition + LN1 -> A-image
    ln_kernel<<<TOK / 8, lnb>>>(x, n1g, n1b, xn, 1);
    // 2) QKV GEMM (100352,192)@(192,576) -> half linear qkv
    tgemm<0><<<dim3(3, 784), 192, SMEM_GEMM>>>(xn, w + OFF_QKVW, qkv_b, qkv, 576, 192, nullptr);
    // 3) windowed attention -> A-image
    attn_kernel<<<NWIN * NHEAD, 128>>>(qkv, msk, att);
    // 4) proj GEMM + un-window/un-shift -> fp32 linear xr
    tgemm<1><<<dim3(1, 784), 192, SMEM_GEMM>>>(att, w + OFF_PROJW, proj_b, xr, 192, 192, nullptr);
    // 5) LN2 -> A-image
    ln_kernel<<<TOK / 8, lnb>>>(xr, n2g, n2b, h, 0);
    // 6) fc1 + exact GELU -> A-image (K=768)
    tgemm<2><<<dim3(4, 784), 192, SMEM_GEMM>>>(h, w + OFF_FC1W, fc1b, h1, 768, 192, nullptr);
    // 7) fc2 + bias + residual -> fp32 out
    tgemm<3><<<dim3(1, 784), 192, SMEM_GEMM>>>(h1, w + OFF_FC2W, fc2b, out, 192, 768, xr);
}

// round 12
// speedup vs baseline: 1.0323x; 1.0323x over previous
#include <cuda_runtime.h>
#include <cuda_fp16.h>
#include <math.h>
#include <stdint.h>

#define TOK   100352          // B*H*W tokens
#define CC    192
#define NHEAD 6
#define HDIM  32
#define NWIN  2048            // B * 64 windows
#define HIDN  768

// Scratch (allocation-free rule: __device__ globals).
__device__ __half g_xn [TOK * CC];        // LN1 out, A-frag image
__device__ __half g_qkv[TOK * 3 * CC];    // qkv, linear half
__device__ __half g_att[TOK * CC];        // attn out, A-frag image
__device__ float  g_xr [TOK * CC];        // residual branch, fp32 linear
__device__ __half g_h  [TOK * CC];        // LN2 out, A-frag image
__device__ __half g_h1 [TOK * HIDN];      // fc1+gelu out, A-frag image
__device__ __half g_w  [442368];          // B-frag images (qkv|proj|fc1|fc2)
__device__ float  g_msk[64 * 49 * 56];    // padded mask [win][r][j56], -1e9 pad

#define OFF_QKVW  0
#define OFF_PROJW 110592
#define OFF_FC1W  147456
#define OFF_FC2W  294912

__device__ __forceinline__ int win_row_to_token(int row) {
    int win = row / 49, n = row % 49;
    int b   = win >> 6, wij = win & 63;
    int wi  = wij >> 3, wj  = wij & 7;
    int hh  = wi * 7 + n / 7;
    int ww  = wj * 7 + n % 7;
    int h = hh + 3; if (h >= 56) h -= 56;
    int w = ww + 3; if (w >= 56) w -= 56;
    return b * 3136 + h * 56 + w;
}

// A-fragment image (half) index for (row, col) of an [*, K] activation (m16n8k16).
__device__ __forceinline__ size_t aimg_idx(int row, int col, int K) {
    int nk  = K >> 5;
    int mb  = row >> 8, m = row & 255;
    int ch  = col >> 5, kin = col & 31;
    int m16 = m >> 4, rr = m & 15;
    int gid = rr & 7, hr = rr >> 3;
    int ks  = kin >> 4, kk = kin & 15;
    int hi  = kk >> 3, q = (kk & 7) >> 1, e = kk & 1;
    int lane = gid * 4 + q;
    int reg  = hi * 2 + hr;
    return ((size_t)mb * nk + ch) * 8192
         + (size_t)((m16 * 2 + ks) * 256 + lane * 8 + reg * 2 + e);
}

// B-fragment image (half) index for weight element (k, n), K the k-dim.
__device__ __forceinline__ size_t bimg_idx(int k, int n, int K) {
    int nk = K >> 5;
    int bx = n >> 6, n64 = n & 63;
    int ch = k >> 5, kin = k & 31;
    int ks = kin >> 4, kk = kin & 15;
    int hi = kk >> 3, q = (kk & 7) >> 1, e = kk & 1;
    int sg = n64 >> 4, ntp = (n64 >> 3) & 1, g = n64 & 7;
    int lane = g * 4 + q;
    return ((size_t)bx * nk + ch) * 2048
         + (size_t)((ks * 4 + sg) * 256 + lane * 8 + ntp * 4 + hi * 2 + e);
}

__device__ __forceinline__ void mma16(float* c, uint4 a, uint32_t b0, uint32_t b1) {
    asm volatile(
        "mma.sync.aligned.m16n8k16.row.col.f32.f16.f16.f32 "
        "{%0,%1,%2,%3},{%4,%5,%6,%7},{%8,%9},{%0,%1,%2,%3};"
        : "+f"(c[0]), "+f"(c[1]), "+f"(c[2]), "+f"(c[3])
        : "r"(a.x), "r"(a.y), "r"(a.z), "r"(a.w), "r"(b0), "r"(b1));
}

// Combined prep: 4 weight B-frag images + padded mask, one launch.
__global__ void prep_all(const float* __restrict__ qkv_w, const float* __restrict__ proj_w,
                         const float* __restrict__ fc1w, const float* __restrict__ fc2w,
                         const float* __restrict__ amask,
                         __half* __restrict__ w, float* __restrict__ msk)
{
    int i = blockIdx.x * 256 + threadIdx.x;
    if (i < 110592) {
        int k = i / 576, n = i % 576;
        w[OFF_QKVW + bimg_idx(k, n, 192)] = __float2half_rn(qkv_w[i]);
    } else if (i < 147456) {
        int j = i - 110592, k = j / 192, n = j % 192;
        w[OFF_PROJW + bimg_idx(k, n, 192)] = __float2half_rn(proj_w[j]);
    } else if (i < 294912) {
        int j = i - 147456, k = j / 768, n = j % 768;
        w[OFF_FC1W + bimg_idx(k, n, 192)] = __float2half_rn(fc1w[j]);
    } else if (i < 442368) {
        int j = i - 294912, k = j / 192, n = j % 192;
        w[OFF_FC2W + bimg_idx(k, n, 768)] = __float2half_rn(fc2w[j]);
    } else if (i < 442368 + 64 * 49 * 56) {
        int j = i - 442368;
        int win = j / 2744, rj = j % 2744, r = rj / 56, jj = rj % 56;
        msk[j] = (jj < 49) ? amask[win * 2401 + r * 49 + jj] : -1e9f;
    }
}

// LayerNorm over C=192, one warp per row; writes half A-frag image.
__global__ void ln_kernel(const float* __restrict__ x, const float* __restrict__ g,
                          const float* __restrict__ bta, __half* __restrict__ out,
                          int permute)
{
    int row  = blockIdx.x * 8 + threadIdx.y;
    int lane = threadIdx.x;
    int src  = permute ? win_row_to_token(row) : row;
    const float* xp = x + (size_t)src * CC;
    float2 v[3];
    float s = 0.f, s2 = 0.f;
#pragma unroll
    for (int i = 0; i < 3; i++) {
        v[i] = *(const float2*)&xp[i * 64 + lane * 2];
        s += v[i].x + v[i].y;
        s2 += v[i].x * v[i].x + v[i].y * v[i].y;
    }
#pragma unroll
    for (int o = 16; o; o >>= 1) {
        s  += __shfl_xor_sync(0xffffffffu, s, o);
        s2 += __shfl_xor_sync(0xffffffffu, s2, o);
    }
    float mu  = s * (1.f / 192.f);
    float var = s2 * (1.f / 192.f) - mu * mu;
    float inv = rsqrtf(var + 1e-5f);
#pragma unroll
    for (int i = 0; i < 3; i++) {
        int c = i * 64 + lane * 2;
        float2 gg = *(const float2*)&g[c];
        float2 bb = *(const float2*)&bta[c];
        float o0 = (v[i].x - mu) * inv * gg.x + bb.x;
        float o1 = (v[i].y - mu) * inv * gg.y + bb.y;
        *(__half2*)&out[aimg_idx(row, c, 192)] = __floats2half2_rn(o0, o1);
    }
}

// FP16 mma.sync GEMM: CTA 256x64, 8 warps (4m x 2n), warp tile 64x32.
// A/B fp16 fragment images, cp.async double buffered. 4 warps/SMSP at occ 2.
// EPI: 0 bias -> half linear; 1 bias+permuted write -> fp32 linear;
//      2 bias+GELU -> half A-image (K'=768); 3 bias+residual -> fp32 linear.
template<int EPI>
__global__ void __launch_bounds__(256, 2)
tgemm(const __half* __restrict__ Aimg, const __half* __restrict__ Bimg,
      const float* __restrict__ bias, void* __restrict__ CoutV,
      int Nn, int K, const float* __restrict__ resid)
{
    extern __shared__ __half dsh[];
    __half* Asm = dsh;                // [2][8192] halves = 32KB
    __half* Bsm = dsh + 2 * 8192;     // [2][2048] halves = 8KB

    const int tid  = threadIdx.x;
    const int warp = tid >> 5, lane = tid & 31;
    const int gid = lane >> 2, qid = lane & 3;
    const int wm = warp >> 1, wn = warp & 1;
    const int bm = blockIdx.y * 256, bn = blockIdx.x * 64;
    const int nk = K >> 5;

    float acc[4][4][4] = {};

    const uint32_t asmb = (uint32_t)__cvta_generic_to_shared(Asm);
    const uint32_t bsmb = asmb + 32768;
    const __half* Ab = Aimg + (size_t)blockIdx.y * nk * 8192;
    const __half* Bb = Bimg + (size_t)blockIdx.x * nk * 2048;

    auto issue = [&](int c) {
        int st = c & 1;
        const uint4* as = (const uint4*)(Ab + (size_t)c * 8192) + tid;
        uint32_t ad = asmb + (uint32_t)(st * 16384 + tid * 16);
#pragma unroll
        for (int p = 0; p < 4; p++)
            asm volatile("cp.async.cg.shared.global [%0], [%1], 16;"
                         :: "r"(ad + p * 4096), "l"(as + p * 256));
        const uint4* bs = (const uint4*)(Bb + (size_t)c * 2048) + tid;
        uint32_t bd = bsmb + (uint32_t)(st * 4096 + tid * 16);
        asm volatile("cp.async.cg.shared.global [%0], [%1], 16;"
                     :: "r"(bd), "l"(bs));
        asm volatile("cp.async.commit_group;" ::: "memory");
    };

    issue(0);
    for (int c = 0; c < nk; c++) {
        if (c + 1 < nk) {
            issue(c + 1);
            asm volatile("cp.async.wait_group 1;" ::: "memory");
        } else {
            asm volatile("cp.async.wait_group 0;" ::: "memory");
        }
        __syncthreads();

        const __half* ab = Asm + (c & 1) * 8192;
        const __half* bb = Bsm + (c & 1) * 2048;
#pragma unroll
        for (int ks = 0; ks < 2; ks++) {
            uint4 fa[4];
#pragma unroll
            for (int mt = 0; mt < 4; mt++)
                fa[mt] = *(const uint4*)&ab[((wm * 4 + mt) * 2 + ks) * 256 + lane * 8];
            uint4 fb0 = *(const uint4*)&bb[(ks * 4 + wn * 2 + 0) * 256 + lane * 8];
            uint4 fb1 = *(const uint4*)&bb[(ks * 4 + wn * 2 + 1) * 256 + lane * 8];
#pragma unroll
            for (int mt = 0; mt < 4; mt++) {
                mma16(acc[mt][0], fa[mt], fb0.x, fb0.y);
                mma16(acc[mt][1], fa[mt], fb0.z, fb0.w);
                mma16(acc[mt][2], fa[mt], fb1.x, fb1.y);
                mma16(acc[mt][3], fa[mt], fb1.z, fb1.w);
            }
        }
        __syncthreads();
    }

    // Epilogue. acc frag: c0:(g,2q) c1:(g,2q+1) c2:(g+8,2q) c3:(g+8,2q+1)
#pragma unroll
    for (int mt = 0; mt < 4; mt++) {
#pragma unroll
        for (int hf = 0; hf < 2; hf++) {
            int row  = bm + wm * 64 + mt * 16 + gid + hf * 8;
            int orow = (EPI == 1) ? win_row_to_token(row) : row;
#pragma unroll
            for (int nt = 0; nt < 4; nt++) {
                int col = bn + wn * 32 + nt * 8 + qid * 2;
                float v0 = acc[mt][nt][hf * 2 + 0] + bias[col];
                float v1 = acc[mt][nt][hf * 2 + 1] + bias[col + 1];
                if (EPI == 0) {
                    __half* O = (__half*)CoutV;
                    *(__half2*)&O[(size_t)row * Nn + col] = __floats2half2_rn(v0, v1);
                } else if (EPI == 1) {
                    float* O = (float*)CoutV;
                    *(float2*)&O[(size_t)orow * Nn + col] = make_float2(v0, v1);
                } else if (EPI == 2) {
                    v0 = 0.5f * v0 * (1.f + erff(v0 * 0.70710678118654752f));
                    v1 = 0.5f * v1 * (1.f + erff(v1 * 0.70710678118654752f));
                    __half* O = (__half*)CoutV;
                    *(__half2*)&O[aimg_idx(row, col, 768)] = __floats2half2_rn(v0, v1);
                } else {
                    float* O = (float*)CoutV;
                    float r0 = resid[(size_t)row * CC + col];
                    float r1 = resid[(size_t)row * CC + col + 1];
                    *(float2*)&O[(size_t)row * Nn + col] = make_float2(v0 + r0, v1 + r1);
                }
            }
        }
    }
}

// FP16 tensor-core attention: one CTA per (window, head), 4 warps.
// (unchanged from round 11)
__global__ void __launch_bounds__(128)
attn_kernel(const __half* __restrict__ qkv, const float* __restrict__ mask2,
            __half* __restrict__ out)
{
    int win  = blockIdx.x / NHEAD;
    int head = blockIdx.x % NHEAD;
    __shared__ __half qa[2048];        // Q A-frag image: 4 m16 x 2 ks x 256
    __shared__ __half kt[56 * 40];     // K [j][d], stride 40
    __shared__ __half vt[32 * 72];     // V^T [d][j], stride 72, j padded to 64
    __shared__ __half pim[4096];       // P A-frag image: 4 m16 x 4 ks x 256

    const int tid = threadIdx.x;
    const int warp = tid >> 5, lane = tid & 31;
    const int gid = lane >> 2, qid = lane & 3;
    const float scale = 0.17677669529663687f;

    {
        uint32_t* z;
        z = (uint32_t*)qa;  for (int t = tid; t < 1024; t += 128) z[t] = 0;
        z = (uint32_t*)kt;  for (int t = tid; t < 1120; t += 128) z[t] = 0;
        z = (uint32_t*)vt;  for (int t = tid; t < 1152; t += 128) z[t] = 0;
        z = (uint32_t*)pim; for (int t = tid; t < 2048; t += 128) z[t] = 0;
    }
    __syncthreads();

    const __half* base = qkv + (size_t)win * 49 * 576;
    for (int t = tid; t < 49 * 16; t += 128) {
        int r = t >> 4, c = (t & 15) * 2;
        __half2 qh = *(const __half2*)&base[r * 576 +       head * 32 + c];
        __half2 kh = *(const __half2*)&base[r * 576 + 192 + head * 32 + c];
        __half2 vh = *(const __half2*)&base[r * 576 + 384 + head * 32 + c];
        float2 qf = __half22float2(qh);
        int m16 = r >> 4, rr = r & 15;
        int ks = c >> 4, kk = c & 15;
        int ln = (rr & 7) * 4 + ((kk & 7) >> 1);
        int reg = (kk >> 3) * 2 + (rr >> 3);
        *(__half2*)&qa[(m16 * 2 + ks) * 256 + ln * 8 + reg * 2] =
            __floats2half2_rn(qf.x * scale, qf.y * scale);
        *(__half2*)&kt[r * 40 + c] = kh;
        vt[c * 72 + r]       = vh.x;
        vt[(c + 1) * 72 + r] = vh.y;
    }
    __syncthreads();

    float sacc[7][4] = {};
#pragma unroll
    for (int ks = 0; ks < 2; ks++) {
        uint4 fa = *(const uint4*)&qa[(warp * 2 + ks) * 256 + lane * 8];
#pragma unroll
        for (int nt = 0; nt < 7; nt++) {
            uint32_t b0 = *(const uint32_t*)&kt[(nt * 8 + gid) * 40 + ks * 16 + qid * 2];
            uint32_t b1 = *(const uint32_t*)&kt[(nt * 8 + gid) * 40 + ks * 16 + 8 + qid * 2];
            mma16(sacc[nt], fa, b0, b1);
        }
    }

    const float* msk = mask2 + (size_t)(win & 63) * 2744;
#pragma unroll
    for (int hf = 0; hf < 2; hf++) {
        int r = warp * 16 + hf * 8 + gid;
        bool ok = (r < 49);
        float v[14];
#pragma unroll
        for (int nt = 0; nt < 7; nt++) {
            float2 mk = ok ? *(const float2*)&msk[r * 56 + nt * 8 + qid * 2]
                           : make_float2(-1e9f, -1e9f);
            v[nt * 2]     = sacc[nt][hf * 2]     + mk.x;
            v[nt * 2 + 1] = sacc[nt][hf * 2 + 1] + mk.y;
        }
        float m = v[0];
#pragma unroll
        for (int i = 1; i < 14; i++) m = fmaxf(m, v[i]);
        m = fmaxf(m, __shfl_xor_sync(0xffffffffu, m, 1));
        m = fmaxf(m, __shfl_xor_sync(0xffffffffu, m, 2));
        float s = 0.f;
#pragma unroll
        for (int i = 0; i < 14; i++) { v[i] = __expf(v[i] - m); s += v[i]; }
        s += __shfl_xor_sync(0xffffffffu, s, 1);
        s += __shfl_xor_sync(0xffffffffu, s, 2);
        float inv = 1.f / s;
#pragma unroll
        for (int nt = 0; nt < 7; nt++) {
            *(__half2*)&pim[(warp * 4 + (nt >> 1)) * 256 + lane * 8 + (nt & 1) * 4 + hf * 2] =
                __floats2half2_rn(v[nt * 2] * inv, v[nt * 2 + 1] * inv);
        }
    }

    float oacc[4][4] = {};
#pragma unroll
    for (int ks = 0; ks < 4; ks++) {
        uint4 fa = *(const uint4*)&pim[(warp * 4 + ks) * 256 + lane * 8];
#pragma unroll
        for (int nt = 0; nt < 4; nt++) {
            uint32_t b0 = *(const uint32_t*)&vt[(nt * 8 + gid) * 72 + ks * 16 + qid * 2];
            uint32_t b1 = *(const uint32_t*)&vt[(nt * 8 + gid) * 72 + ks * 16 + 8 + qid * 2];
            mma16(oacc[nt], fa, b0, b1);
        }
    }

    int i0 = warp * 16 + gid, i1 = warp * 16 + 8 + gid;
#pragma unroll
    for (int nt = 0; nt < 4; nt++) {
        int d = head * 32 + nt * 8 + qid * 2;
        if (i0 < 49) {
            int r0 = win * 49 + i0;
            *(__half2*)&out[aimg_idx(r0, d, 192)] =
                __floats2half2_rn(oacc[nt][0], oacc[nt][1]);
        }
        if (i1 < 49) {
            int r1 = win * 49 + i1;
            *(__half2*)&out[aimg_idx(r1, d, 192)] =
                __floats2half2_rn(oacc[nt][2], oacc[nt][3]);
        }
    }
}

extern "C" void kernel_launch(void* const* d_in, const int* in_sizes, int n_in,
                              void* d_out, int out_size)
{
    const float* x      = (const float*)d_in[0];
    const float* qkv_w  = (const float*)d_in[1];
    const float* qkv_b  = (const float*)d_in[2];
    const float* proj_w = (const float*)d_in[3];
    const float* proj_b = (const float*)d_in[4];
    const float* n1g    = (const float*)d_in[5];
    const float* n1b    = (const float*)d_in[6];
    const float* n2g    = (const float*)d_in[7];
    const float* n2b    = (const float*)d_in[8];
    const float* fc1w   = (const float*)d_in[9];
    const float* fc1b   = (const float*)d_in[10];
    const float* fc2w   = (const float*)d_in[11];
    const float* fc2b   = (const float*)d_in[12];
    const float* amask  = (const float*)d_in[13];
    float* out = (float*)d_out;

    __half *xn, *qkv, *att, *h, *h1, *w;
    float *xr, *msk;
    cudaGetSymbolAddress((void**)&xn,  g_xn);
    cudaGetSymbolAddress((void**)&qkv, g_qkv);
    cudaGetSymbolAddress((void**)&att, g_att);
    cudaGetSymbolAddress((void**)&xr,  g_xr);
    cudaGetSymbolAddress((void**)&h,   g_h);
    cudaGetSymbolAddress((void**)&h1,  g_h1);
    cudaGetSymbolAddress((void**)&w,   g_w);
    cudaGetSymbolAddress((void**)&msk, g_msk);

    const int SMEM_GEMM = 40960;   // 32KB A + 8KB B
    cudaFuncSetAttribute(tgemm<0>, cudaFuncAttributeMaxDynamicSharedMemorySize, SMEM_GEMM);
    cudaFuncSetAttribute(tgemm<1>, cudaFuncAttributeMaxDynamicSharedMemorySize, SMEM_GEMM);
    cudaFuncSetAttribute(tgemm<2>, cudaFuncAttributeMaxDynamicSharedMemorySize, SMEM_GEMM);
    cudaFuncSetAttribute(tgemm<3>, cudaFuncAttributeMaxDynamicSharedMemorySize, SMEM_GEMM);

    // 0) build B fragment images + padded mask (one launch)
    prep_all<<<(442368 + 64 * 49 * 56 + 255) / 256, 256>>>(
        qkv_w, proj_w, fc1w, fc2w, amask, w, msk);

    dim3 lnb(32, 8);
    // 1) shift + window partition + LN1 -> A-image
    ln_kernel<<<TOK / 8, lnb>>>(x, n1g, n1b, xn, 1);
    // 2) QKV GEMM (100352,192)@(192,576) -> half linear qkv
    tgemm<0><<<dim3(9, 392), 256, SMEM_GEMM>>>(xn, w + OFF_QKVW, qkv_b, qkv, 576, 192, nullptr);
    // 3) windowed attention -> A-image
    attn_kernel<<<NWIN * NHEAD, 128>>>(qkv, msk, att);
    // 4) proj GEMM + un-window/un-shift -> fp32 linear xr
    tgemm<1><<<dim3(3, 392), 256, SMEM_GEMM>>>(att, w + OFF_PROJW, proj_b, xr, 192, 192, nullptr);
    // 5) LN2 -> A-image
    ln_kernel<<<TOK / 8, lnb>>>(xr, n2g, n2b, h, 0);
    // 6) fc1 + exact GELU -> A-image (K=768)
    tgemm<2><<<dim3(12, 392), 256, SMEM_GEMM>>>(h, w + OFF_FC1W, fc1b, h1, 768, 192, nullptr);
    // 7) fc2 + bias + residual -> fp32 out
    tgemm<3><<<dim3(3, 392), 256, SMEM_GEMM>>>(h1, w + OFF_FC2W, fc2b, out, 192, 768, xr);
}

// round 14
// speedup vs baseline: 1.0634x; 1.0301x over previous
#include <cuda_runtime.h>
#include <cuda_fp16.h>
#include <math.h>
#include <stdint.h>

#define TOK   100352          // B*H*W tokens
#define CC    192
#define NHEAD 6
#define HDIM  32
#define NWIN  2048            // B * 64 windows
#define HIDN  768

// Scratch (allocation-free rule: __device__ globals).
__device__ __half g_xn [TOK * CC];        // LN1 out, A-frag image
__device__ __half g_qkv[TOK * 3 * CC];    // qkv, linear half
__device__ __half g_att[TOK * CC];        // attn out, A-frag image
__device__ float  g_xr [TOK * CC];        // residual branch, fp32 linear
__device__ __half g_h  [TOK * CC];        // LN2 out, A-frag image
__device__ __half g_h1 [TOK * HIDN];      // fc1+gelu out, A-frag image
__device__ __half g_w  [442368];          // B-frag images (qkv|proj|fc1|fc2)
__device__ float  g_msk[64 * 49 * 56];    // padded mask [win][r][j56], -1e9 pad

#define OFF_QKVW  0
#define OFF_PROJW 110592
#define OFF_FC1W  147456
#define OFF_FC2W  294912

__device__ __forceinline__ int win_row_to_token(int row) {
    int win = row / 49, n = row % 49;
    int b   = win >> 6, wij = win & 63;
    int wi  = wij >> 3, wj  = wij & 7;
    int hh  = wi * 7 + n / 7;
    int ww  = wj * 7 + n % 7;
    int h = hh + 3; if (h >= 56) h -= 56;
    int w = ww + 3; if (w >= 56) w -= 56;
    return b * 3136 + h * 56 + w;
}

__device__ __forceinline__ uint32_t h2_as_u32(__half2 v) {
    return *reinterpret_cast<uint32_t*>(&v);
}

// A-fragment image (half) index for (row, col) of an [*, K] activation (m16n8k16).
__device__ __forceinline__ size_t aimg_idx(int row, int col, int K) {
    int nk  = K >> 5;
    int mb  = row >> 8, m = row & 255;
    int ch  = col >> 5, kin = col & 31;
    int m16 = m >> 4, rr = m & 15;
    int gid = rr & 7, hr = rr >> 3;
    int ks  = kin >> 4, kk = kin & 15;
    int hi  = kk >> 3, q = (kk & 7) >> 1, e = kk & 1;
    int lane = gid * 4 + q;
    int reg  = hi * 2 + hr;
    return ((size_t)mb * nk + ch) * 8192
         + (size_t)((m16 * 2 + ks) * 256 + lane * 8 + reg * 2 + e);
}

// B-fragment image (half) index for weight element (k, n), K the k-dim.
__device__ __forceinline__ size_t bimg_idx(int k, int n, int K) {
    int nk = K >> 5;
    int bx = n >> 6, n64 = n & 63;
    int ch = k >> 5, kin = k & 31;
    int ks = kin >> 4, kk = kin & 15;
    int hi = kk >> 3, q = (kk & 7) >> 1, e = kk & 1;
    int sg = n64 >> 4, ntp = (n64 >> 3) & 1, g = n64 & 7;
    int lane = g * 4 + q;
    return ((size_t)bx * nk + ch) * 2048
         + (size_t)((ks * 4 + sg) * 256 + lane * 8 + ntp * 4 + hi * 2 + e);
}

__device__ __forceinline__ void mma16(float* c, uint4 a, uint32_t b0, uint32_t b1) {
    asm volatile(
        "mma.sync.aligned.m16n8k16.row.col.f32.f16.f16.f32 "
        "{%0,%1,%2,%3},{%4,%5,%6,%7},{%8,%9},{%0,%1,%2,%3};"
        : "+f"(c[0]), "+f"(c[1]), "+f"(c[2]), "+f"(c[3])
        : "r"(a.x), "r"(a.y), "r"(a.z), "r"(a.w), "r"(b0), "r"(b1));
}

// Combined prep: 4 weight B-frag images + padded mask, one launch.
__global__ void prep_all(const float* __restrict__ qkv_w, const float* __restrict__ proj_w,
                         const float* __restrict__ fc1w, const float* __restrict__ fc2w,
                         const float* __restrict__ amask,
                         __half* __restrict__ w, float* __restrict__ msk)
{
    int i = blockIdx.x * 256 + threadIdx.x;
    if (i < 110592) {
        int k = i / 576, n = i % 576;
        w[OFF_QKVW + bimg_idx(k, n, 192)] = __float2half_rn(qkv_w[i]);
    } else if (i < 147456) {
        int j = i - 110592, k = j / 192, n = j % 192;
        w[OFF_PROJW + bimg_idx(k, n, 192)] = __float2half_rn(proj_w[j]);
    } else if (i < 294912) {
        int j = i - 147456, k = j / 768, n = j % 768;
        w[OFF_FC1W + bimg_idx(k, n, 192)] = __float2half_rn(fc1w[j]);
    } else if (i < 442368) {
        int j = i - 294912, k = j / 192, n = j % 192;
        w[OFF_FC2W + bimg_idx(k, n, 768)] = __float2half_rn(fc2w[j]);
    } else if (i < 442368 + 64 * 49 * 56) {
        int j = i - 442368;
        int win = j / 2744, rj = j % 2744, r = rj / 56, jj = rj % 56;
        msk[j] = (jj < 49) ? amask[win * 2401 + r * 49 + jj] : -1e9f;
    }
}

// LayerNorm over C=192, one warp per row; writes half A-frag image.
__global__ void ln_kernel(const float* __restrict__ x, const float* __restrict__ g,
                          const float* __restrict__ bta, __half* __restrict__ out,
                          int permute)
{
    int row  = blockIdx.x * 8 + threadIdx.y;
    int lane = threadIdx.x;
    int src  = permute ? win_row_to_token(row) : row;
    const float* xp = x + (size_t)src * CC;
    float2 v[3];
    float s = 0.f, s2 = 0.f;
#pragma unroll
    for (int i = 0; i < 3; i++) {
        v[i] = *(const float2*)&xp[i * 64 + lane * 2];
        s += v[i].x + v[i].y;
        s2 += v[i].x * v[i].x + v[i].y * v[i].y;
    }
#pragma unroll
    for (int o = 16; o; o >>= 1) {
        s  += __shfl_xor_sync(0xffffffffu, s, o);
        s2 += __shfl_xor_sync(0xffffffffu, s2, o);
    }
    float mu  = s * (1.f / 192.f);
    float var = s2 * (1.f / 192.f) - mu * mu;
    float inv = rsqrtf(var + 1e-5f);
#pragma unroll
    for (int i = 0; i < 3; i++) {
        int c = i * 64 + lane * 2;
        float2 gg = *(const float2*)&g[c];
        float2 bb = *(const float2*)&bta[c];
        float o0 = (v[i].x - mu) * inv * gg.x + bb.x;
        float o1 = (v[i].y - mu) * inv * gg.y + bb.y;
        *(__half2*)&out[aimg_idx(row, c, 192)] = __floats2half2_rn(o0, o1);
    }
}

// FP16 mma.sync GEMM: CTA 256x64, 8 warps (4m x 2n), warp tile 64x32.
// EPI: 0 bias -> half linear; 2 bias+GELU -> half A-image (K'=768);
//      3 bias+residual -> fp32 linear.
template<int EPI>
__global__ void __launch_bounds__(256, 2)
tgemm(const __half* __restrict__ Aimg, const __half* __restrict__ Bimg,
      const float* __restrict__ bias, void* __restrict__ CoutV,
      int Nn, int K, const float* __restrict__ resid)
{
    extern __shared__ __half dsh[];
    __half* Asm = dsh;                // [2][8192] halves = 32KB
    __half* Bsm = dsh + 2 * 8192;     // [2][2048] halves = 8KB

    const int tid  = threadIdx.x;
    const int warp = tid >> 5, lane = tid & 31;
    const int gid = lane >> 2, qid = lane & 3;
    const int wm = warp >> 1, wn = warp & 1;
    const int bm = blockIdx.y * 256, bn = blockIdx.x * 64;
    const int nk = K >> 5;

    float acc[4][4][4] = {};

    const uint32_t asmb = (uint32_t)__cvta_generic_to_shared(Asm);
    const uint32_t bsmb = asmb + 32768;
    const __half* Ab = Aimg + (size_t)blockIdx.y * nk * 8192;
    const __half* Bb = Bimg + (size_t)blockIdx.x * nk * 2048;

    auto issue = [&](int c) {
        int st = c & 1;
        const uint4* as = (const uint4*)(Ab + (size_t)c * 8192) + tid;
        uint32_t ad = asmb + (uint32_t)(st * 16384 + tid * 16);
#pragma unroll
        for (int p = 0; p < 4; p++)
            asm volatile("cp.async.cg.shared.global [%0], [%1], 16;"
                         :: "r"(ad + p * 4096), "l"(as + p * 256));
        const uint4* bs = (const uint4*)(Bb + (size_t)c * 2048) + tid;
        uint32_t bd = bsmb + (uint32_t)(st * 4096 + tid * 16);
        asm volatile("cp.async.cg.shared.global [%0], [%1], 16;"
                     :: "r"(bd), "l"(bs));
        asm volatile("cp.async.commit_group;" ::: "memory");
    };

    issue(0);
    for (int c = 0; c < nk; c++) {
        if (c + 1 < nk) {
            issue(c + 1);
            asm volatile("cp.async.wait_group 1;" ::: "memory");
        } else {
            asm volatile("cp.async.wait_group 0;" ::: "memory");
        }
        __syncthreads();

        const __half* ab = Asm + (c & 1) * 8192;
        const __half* bb = Bsm + (c & 1) * 2048;
#pragma unroll
        for (int ks = 0; ks < 2; ks++) {
            uint4 fa[4];
#pragma unroll
            for (int mt = 0; mt < 4; mt++)
                fa[mt] = *(const uint4*)&ab[((wm * 4 + mt) * 2 + ks) * 256 + lane * 8];
            uint4 fb0 = *(const uint4*)&bb[(ks * 4 + wn * 2 + 0) * 256 + lane * 8];
            uint4 fb1 = *(const uint4*)&bb[(ks * 4 + wn * 2 + 1) * 256 + lane * 8];
#pragma unroll
            for (int mt = 0; mt < 4; mt++) {
                mma16(acc[mt][0], fa[mt], fb0.x, fb0.y);
                mma16(acc[mt][1], fa[mt], fb0.z, fb0.w);
                mma16(acc[mt][2], fa[mt], fb1.x, fb1.y);
                mma16(acc[mt][3], fa[mt], fb1.z, fb1.w);
            }
        }
        __syncthreads();
    }

#pragma unroll
    for (int mt = 0; mt < 4; mt++) {
#pragma unroll
        for (int hf = 0; hf < 2; hf++) {
            int row = bm + wm * 64 + mt * 16 + gid + hf * 8;
#pragma unroll
            for (int nt = 0; nt < 4; nt++) {
                int col = bn + wn * 32 + nt * 8 + qid * 2;
                float v0 = acc[mt][nt][hf * 2 + 0] + bias[col];
                float v1 = acc[mt][nt][hf * 2 + 1] + bias[col + 1];
                if (EPI == 0) {
                    __half* O = (__half*)CoutV;
                    *(__half2*)&O[(size_t)row * Nn + col] = __floats2half2_rn(v0, v1);
                } else if (EPI == 2) {
                    v0 = 0.5f * v0 * (1.f + erff(v0 * 0.70710678118654752f));
                    v1 = 0.5f * v1 * (1.f + erff(v1 * 0.70710678118654752f));
                    __half* O = (__half*)CoutV;
                    *(__half2*)&O[aimg_idx(row, col, 768)] = __floats2half2_rn(v0, v1);
                } else {
                    float* O = (float*)CoutV;
                    float r0 = resid[(size_t)row * CC + col];
                    float r1 = resid[(size_t)row * CC + col + 1];
                    *(float2*)&O[(size_t)row * Nn + col] = make_float2(v0 + r0, v1 + r1);
                }
            }
        }
    }
}

// proj GEMM + un-window/un-shift + fused LN2.
// CTA 128x192 (full row), 6 warps (2m x 3n), warp tile 64x64.
// Writes xr (fp32 linear, token order) AND h = LN2(xr) (half A-image).
__global__ void __launch_bounds__(192, 2)
projln(const __half* __restrict__ Aimg, const __half* __restrict__ Bimg,
       const float* __restrict__ bias, float* __restrict__ xr,
       __half* __restrict__ hout,
       const float* __restrict__ n2g, const float* __restrict__ n2b)
{
    extern __shared__ __half dsh[];
    __half* Asm = dsh;                // [2][4096] halves = 16KB
    __half* Bsm = dsh + 2 * 4096;     // [2][6144] halves = 24KB
    float* redS = (float*)(dsh + 2 * 4096 + 2 * 6144);   // [3][128]
    float* redQ = redS + 3 * 128;                        // [3][128]

    const int tid  = threadIdx.x;
    const int warp = tid >> 5, lane = tid & 31;
    const int gid = lane >> 2, qid = lane & 3;
    const int wm = warp / 3, wn = warp % 3;
    const int bm = blockIdx.y * 128;
    const int nk = 6;   // K = 192

    float acc[4][8][4] = {};

    const uint32_t asmb = (uint32_t)__cvta_generic_to_shared(Asm);
    const uint32_t bsmb = asmb + 16384;
    const __half* Ab = Aimg + (size_t)(bm >> 8) * nk * 8192 + ((bm >> 7) & 1) * 4096;

    auto issue = [&](int c) {
        int st = c & 1;
        const uint4* as = (const uint4*)(Ab + (size_t)c * 8192);
        uint32_t ad = asmb + (uint32_t)(st * 8192);
#pragma unroll
        for (int p = 0; p < 3; p++) {
            int idx = tid + p * 192;
            if (p < 2 || idx < 512)
                asm volatile("cp.async.cg.shared.global [%0], [%1], 16;"
                             :: "r"(ad + idx * 16), "l"(as + idx));
        }
        uint32_t bd = bsmb + (uint32_t)(st * 12288);
#pragma unroll
        for (int p = 0; p < 4; p++) {
            int idx = tid + p * 192;          // 0..767 (3 x-blocks x 256 uint4)
            int xb = idx >> 8, off = idx & 255;
            const uint4* bs = (const uint4*)(Bimg + ((size_t)xb * nk + c) * 2048) + off;
            asm volatile("cp.async.cg.shared.global [%0], [%1], 16;"
                         :: "r"(bd + idx * 16), "l"(bs));
        }
        asm volatile("cp.async.commit_group;" ::: "memory");
    };

    issue(0);
    for (int c = 0; c < nk; c++) {
        if (c + 1 < nk) {
            issue(c + 1);
            asm volatile("cp.async.wait_group 1;" ::: "memory");
        } else {
            asm volatile("cp.async.wait_group 0;" ::: "memory");
        }
        __syncthreads();

        const __half* ab = Asm + (c & 1) * 4096;
        const __half* bb = Bsm + (c & 1) * 6144 + wn * 2048;
#pragma unroll
        for (int ks = 0; ks < 2; ks++) {
            uint4 fa[4];
#pragma unroll
            for (int mt = 0; mt < 4; mt++)
                fa[mt] = *(const uint4*)&ab[(((wm * 4 + mt) * 2) + ks) * 256 + lane * 8];
#pragma unroll
            for (int s = 0; s < 4; s++) {
                uint4 fb = *(const uint4*)&bb[(ks * 4 + s) * 256 + lane * 8];
#pragma unroll
                for (int mt = 0; mt < 4; mt++) {
                    mma16(acc[mt][s * 2],     fa[mt], fb.x, fb.y);
                    mma16(acc[mt][s * 2 + 1], fa[mt], fb.z, fb.w);
                }
            }
        }
        __syncthreads();
    }

    // Row-sum partials (quad shuffle over 64 cols, per wn), then combine.
#pragma unroll
    for (int mt = 0; mt < 4; mt++) {
#pragma unroll
        for (int hf = 0; hf < 2; hf++) {
            float s = 0.f, q2 = 0.f;
#pragma unroll
            for (int nt = 0; nt < 8; nt++) {
                int col = wn * 64 + nt * 8 + qid * 2;
                float v0 = acc[mt][nt][hf * 2 + 0] + bias[col];
                float v1 = acc[mt][nt][hf * 2 + 1] + bias[col + 1];
                s += v0 + v1;
                q2 += v0 * v0 + v1 * v1;
            }
            s  += __shfl_xor_sync(0xffffffffu, s, 1);
            s  += __shfl_xor_sync(0xffffffffu, s, 2);
            q2 += __shfl_xor_sync(0xffffffffu, q2, 1);
            q2 += __shfl_xor_sync(0xffffffffu, q2, 2);
            if (qid == 0) {
                int ridx = wm * 64 + mt * 16 + hf * 8 + gid;
                redS[wn * 128 + ridx] = s;
                redQ[wn * 128 + ridx] = q2;
            }
        }
    }
    __syncthreads();

#pragma unroll
    for (int mt = 0; mt < 4; mt++) {
#pragma unroll
        for (int hf = 0; hf < 2; hf++) {
            int ridx = wm * 64 + mt * 16 + hf * 8 + gid;
            int row  = bm + ridx;
            int orow = win_row_to_token(row);
            float S  = redS[ridx] + redS[128 + ridx] + redS[256 + ridx];
            float Q  = redQ[ridx] + redQ[128 + ridx] + redQ[256 + ridx];
            float mu = S * (1.f / 192.f);
            float var = Q * (1.f / 192.f) - mu * mu;
            float inv = rsqrtf(var + 1e-5f);
#pragma unroll
            for (int nt = 0; nt < 8; nt++) {
                int col = wn * 64 + nt * 8 + qid * 2;
                float v0 = acc[mt][nt][hf * 2 + 0] + bias[col];
                float v1 = acc[mt][nt][hf * 2 + 1] + bias[col + 1];
                *(float2*)&xr[(size_t)orow * CC + col] = make_float2(v0, v1);
                float2 gg = *(const float2*)&n2g[col];
                float2 bb = *(const float2*)&n2b[col];
                float h0 = (v0 - mu) * inv * gg.x + bb.x;
                float h1 = (v1 - mu) * inv * gg.y + bb.y;
                *(__half2*)&hout[aimg_idx(orow, col, 192)] = __floats2half2_rn(h0, h1);
            }
        }
    }
}

// FP16 tensor-core attention: one CTA per (window, head), 4 warps.
// P fragments built entirely in registers (no smem round trip).
__global__ void __launch_bounds__(128)
attn_kernel(const __half* __restrict__ qkv, const float* __restrict__ mask2,
            __half* __restrict__ out)
{
    int win  = blockIdx.x / NHEAD;
    int head = blockIdx.x % NHEAD;
    __shared__ __half qa[2048];        // Q A-frag image: 4 m16 x 2 ks x 256
    __shared__ __half kt[56 * 40];     // K [j][d], stride 40
    __shared__ __half vt[32 * 72];     // V^T [d][j], stride 72, j padded to 64

    const int tid = threadIdx.x;
    const int warp = tid >> 5, lane = tid & 31;
    const int gid = lane >> 2, qid = lane & 3;
    const float scale = 0.17677669529663687f;

    {
        uint32_t* z;
        z = (uint32_t*)qa;  for (int t = tid; t < 1024; t += 128) z[t] = 0;
        z = (uint32_t*)kt;  for (int t = tid; t < 1120; t += 128) z[t] = 0;
        z = (uint32_t*)vt;  for (int t = tid; t < 1152; t += 128) z[t] = 0;
    }
    __syncthreads();

    const __half* base = qkv + (size_t)win * 49 * 576;
    for (int t = tid; t < 49 * 16; t += 128) {
        int r = t >> 4, c = (t & 15) * 2;
        __half2 qh = *(const __half2*)&base[r * 576 +       head * 32 + c];
        __half2 kh = *(const __half2*)&base[r * 576 + 192 + head * 32 + c];
        __half2 vh = *(const __half2*)&base[r * 576 + 384 + head * 32 + c];
        float2 qf = __half22float2(qh);
        int m16 = r >> 4, rr = r & 15;
        int ks = c >> 4, kk = c & 15;
        int ln = (rr & 7) * 4 + ((kk & 7) >> 1);
        int reg = (kk >> 3) * 2 + (rr >> 3);
        *(__half2*)&qa[(m16 * 2 + ks) * 256 + ln * 8 + reg * 2] =
            __floats2half2_rn(qf.x * scale, qf.y * scale);
        *(__half2*)&kt[r * 40 + c] = kh;
        vt[c * 72 + r]       = vh.x;
        vt[(c + 1) * 72 + r] = vh.y;
    }
    __syncthreads();

    float sacc[7][4] = {};
#pragma unroll
    for (int ks = 0; ks < 2; ks++) {
        uint4 fa = *(const uint4*)&qa[(warp * 2 + ks) * 256 + lane * 8];
#pragma unroll
        for (int nt = 0; nt < 7; nt++) {
            uint32_t b0 = *(const uint32_t*)&kt[(nt * 8 + gid) * 40 + ks * 16 + qid * 2];
            uint32_t b1 = *(const uint32_t*)&kt[(nt * 8 + gid) * 40 + ks * 16 + 8 + qid * 2];
            mma16(sacc[nt], fa, b0, b1);
        }
    }

    // In-register masked softmax; P half2 fragments kept in registers.
    const float* msk = mask2 + (size_t)(win & 63) * 2744;
    uint32_t ph[2][8];
    ph[0][7] = 0u; ph[1][7] = 0u;      // j 56..63 pad = 0
#pragma unroll
    for (int hf = 0; hf < 2; hf++) {
        int r = warp * 16 + hf * 8 + gid;
        bool ok = (r < 49);
        float v[14];
#pragma unroll
        for (int nt = 0; nt < 7; nt++) {
            float2 mk = ok ? *(const float2*)&msk[r * 56 + nt * 8 + qid * 2]
                           : make_float2(-1e9f, -1e9f);
            v[nt * 2]     = sacc[nt][hf * 2]     + mk.x;
            v[nt * 2 + 1] = sacc[nt][hf * 2 + 1] + mk.y;
        }
        float m = v[0];
#pragma unroll
        for (int i = 1; i < 14; i++) m = fmaxf(m, v[i]);
        m = fmaxf(m, __shfl_xor_sync(0xffffffffu, m, 1));
        m = fmaxf(m, __shfl_xor_sync(0xffffffffu, m, 2));
        float s = 0.f;
#pragma unroll
        for (int i = 0; i < 14; i++) { v[i] = __expf(v[i] - m); s += v[i]; }
        s += __shfl_xor_sync(0xffffffffu, s, 1);
        s += __shfl_xor_sync(0xffffffffu, s, 2);
        float inv = 1.f / s;
#pragma unroll
        for (int nt = 0; nt < 7; nt++)
            ph[hf][nt] = h2_as_u32(
                __floats2half2_rn(v[nt * 2] * inv, v[nt * 2 + 1] * inv));
    }

    // O = P V : A-fragments assembled from ph registers (lane-identity).
    float oacc[4][4] = {};
#pragma unroll
    for (int ks = 0; ks < 4; ks++) {
        uint4 fa = make_uint4(ph[0][2 * ks], ph[1][2 * ks],
                              ph[0][2 * ks + 1], ph[1][2 * ks + 1]);
#pragma unroll
        for (int nt = 0; nt < 4; nt++) {
            uint32_t b0 = *(const uint32_t*)&vt[(nt * 8 + gid) * 72 + ks * 16 + qid * 2];
            uint32_t b1 = *(const uint32_t*)&vt[(nt * 8 + gid) * 72 + ks * 16 + 8 + qid * 2];
            mma16(oacc[nt], fa, b0, b1);
        }
    }

    int i0 = warp * 16 + gid, i1 = warp * 16 + 8 + gid;
#pragma unroll
    for (int nt = 0; nt < 4; nt++) {
        int d = head * 32 + nt * 8 + qid * 2;
        if (i0 < 49) {
            int r0 = win * 49 + i0;
            *(__half2*)&out[aimg_idx(r0, d, 192)] =
                __floats2half2_rn(oacc[nt][0], oacc[nt][1]);
        }
        if (i1 < 49) {
            int r1 = win * 49 + i1;
            *(__half2*)&out[aimg_idx(r1, d, 192)] =
                __floats2half2_rn(oacc[nt][2], oacc[nt][3]);
        }
    }
}

extern "C" void kernel_launch(void* const* d_in, const int* in_sizes, int n_in,
                              void* d_out, int out_size)
{
    const float* x      = (const float*)d_in[0];
    const float* qkv_w  = (const float*)d_in[1];
    const float* qkv_b  = (const float*)d_in[2];
    const float* proj_w = (const float*)d_in[3];
    const float* proj_b = (const float*)d_in[4];
    const float* n1g    = (const float*)d_in[5];
    const float* n1b    = (const float*)d_in[6];
    const float* n2g    = (const float*)d_in[7];
    const float* n2b    = (const float*)d_in[8];
    const float* fc1w   = (const float*)d_in[9];
    const float* fc1b   = (const float*)d_in[10];
    const float* fc2w   = (const float*)d_in[11];
    const float* fc2b   = (const float*)d_in[12];
    const float* amask  = (const float*)d_in[13];
    float* out = (float*)d_out;

    __half *xn, *qkv, *att, *h, *h1, *w;
    float *xr, *msk;
    cudaGetSymbolAddress((void**)&xn,  g_xn);
    cudaGetSymbolAddress((void**)&qkv, g_qkv);
    cudaGetSymbolAddress((void**)&att, g_att);
    cudaGetSymbolAddress((void**)&xr,  g_xr);
    cudaGetSymbolAddress((void**)&h,   g_h);
    cudaGetSymbolAddress((void**)&h1,  g_h1);
    cudaGetSymbolAddress((void**)&w,   g_w);
    cudaGetSymbolAddress((void**)&msk, g_msk);

    const int SMEM_GEMM = 40960;    // 32KB A + 8KB B
    const int SMEM_PROJ = 40960 + 3072;  // 16KB A + 24KB B + 3KB LN reduce
    cudaFuncSetAttribute(tgemm<0>, cudaFuncAttributeMaxDynamicSharedMemorySize, SMEM_GEMM);
    cudaFuncSetAttribute(tgemm<2>, cudaFuncAttributeMaxDynamicSharedMemorySize, SMEM_GEMM);
    cudaFuncSetAttribute(tgemm<3>, cudaFuncAttributeMaxDynamicSharedMemorySize, SMEM_GEMM);
    cudaFuncSetAttribute(projln,   cudaFuncAttributeMaxDynamicSharedMemorySize, SMEM_PROJ);

    // 0) build B fragment images + padded mask (one launch)
    prep_all<<<(442368 + 64 * 49 * 56 + 255) / 256, 256>>>(
        qkv_w, proj_w, fc1w, fc2w, amask, w, msk);

    dim3 lnb(32, 8);
    // 1) shift + window partition + LN1 -> A-image
    ln_kernel<<<TOK / 8, lnb>>>(x, n1g, n1b, xn, 1);
    // 2) QKV GEMM (100352,192)@(192,576) -> half linear qkv
    tgemm<0><<<dim3(9, 392), 256, SMEM_GEMM>>>(xn, w + OFF_QKVW, qkv_b, qkv, 576, 192, nullptr);
    // 3) windowed attention -> A-image
    attn_kernel<<<NWIN * NHEAD, 128>>>(qkv, msk, att);
    // 4) proj GEMM + un-window/un-shift + fused LN2 -> xr (fp32) and h (A-image)
    projln<<<dim3(1, 784), 192, SMEM_PROJ>>>(att, w + OFF_PROJW, proj_b, xr, h, n2g, n2b);
    // 5) fc1 + exact GELU -> A-image (K=768)
    tgemm<2><<<dim3(12, 392), 256, SMEM_GEMM>>>(h, w + OFF_FC1W, fc1b, h1, 768, 192, nullptr);
    // 6) fc2 + bias + residual -> fp32 out
    tgemm<3><<<dim3(3, 392), 256, SMEM_GEMM>>>(h1, w + OFF_FC2W, fc2b, out, 192, 768, xr);
}

// round 15
// speedup vs baseline: 1.0982x; 1.0327x over previous
#include <cuda_runtime.h>
#include <cuda_fp16.h>
#include <math.h>
#include <stdint.h>

#define TOK   100352          // B*H*W tokens
#define CC    192
#define NHEAD 6
#define HDIM  32
#define NWIN  2048            // B * 64 windows
#define HIDN  768

// Scratch (allocation-free rule: __device__ globals).
__device__ __half g_xn [TOK * CC];        // LN1 out, A-frag image
__device__ __half g_qkv[TOK * 3 * CC];    // qkv, linear half
__device__ __half g_att[TOK * CC];        // attn out, A-frag image
__device__ float  g_xr [TOK * CC];        // residual branch, fp32 linear
__device__ __half g_h  [TOK * CC];        // LN2 out, A-frag image
__device__ __half g_h1 [TOK * HIDN];      // fc1+gelu out, A-frag image
__device__ __half g_w  [442368];          // B-frag images (qkv|proj|fc1|fc2)
__device__ float  g_msk[64 * 49 * 56];    // padded mask [win][r][j56], -1e9 pad

#define OFF_QKVW  0
#define OFF_PROJW 110592
#define OFF_FC1W  147456
#define OFF_FC2W  294912

__device__ __forceinline__ int win_row_to_token(int row) {
    int win = row / 49, n = row % 49;
    int b   = win >> 6, wij = win & 63;
    int wi  = wij >> 3, wj  = wij & 7;
    int hh  = wi * 7 + n / 7;
    int ww  = wj * 7 + n % 7;
    int h = hh + 3; if (h >= 56) h -= 56;
    int w = ww + 3; if (w >= 56) w -= 56;
    return b * 3136 + h * 56 + w;
}

__device__ __forceinline__ uint32_t h2_as_u32(__half2 v) {
    return *reinterpret_cast<uint32_t*>(&v);
}

// A-fragment image (half) index for (row, col) of an [*, K] activation (m16n8k16).
__device__ __forceinline__ size_t aimg_idx(int row, int col, int K) {
    int nk  = K >> 5;
    int mb  = row >> 8, m = row & 255;
    int ch  = col >> 5, kin = col & 31;
    int m16 = m >> 4, rr = m & 15;
    int gid = rr & 7, hr = rr >> 3;
    int ks  = kin >> 4, kk = kin & 15;
    int hi  = kk >> 3, q = (kk & 7) >> 1, e = kk & 1;
    int lane = gid * 4 + q;
    int reg  = hi * 2 + hr;
    return ((size_t)mb * nk + ch) * 8192
         + (size_t)((m16 * 2 + ks) * 256 + lane * 8 + reg * 2 + e);
}

// B-fragment image (half) index for weight element (k, n), K the k-dim.
__device__ __forceinline__ size_t bimg_idx(int k, int n, int K) {
    int nk = K >> 5;
    int bx = n >> 6, n64 = n & 63;
    int ch = k >> 5, kin = k & 31;
    int ks = kin >> 4, kk = kin & 15;
    int hi = kk >> 3, q = (kk & 7) >> 1, e = kk & 1;
    int sg = n64 >> 4, ntp = (n64 >> 3) & 1, g = n64 & 7;
    int lane = g * 4 + q;
    return ((size_t)bx * nk + ch) * 2048
         + (size_t)((ks * 4 + sg) * 256 + lane * 8 + ntp * 4 + hi * 2 + e);
}

__device__ __forceinline__ void mma16(float* c, uint4 a, uint32_t b0, uint32_t b1) {
    asm volatile(
        "mma.sync.aligned.m16n8k16.row.col.f32.f16.f16.f32 "
        "{%0,%1,%2,%3},{%4,%5,%6,%7},{%8,%9},{%0,%1,%2,%3};"
        : "+f"(c[0]), "+f"(c[1]), "+f"(c[2]), "+f"(c[3])
        : "r"(a.x), "r"(a.y), "r"(a.z), "r"(a.w), "r"(b0), "r"(b1));
}

// Combined prep: 4 weight B-frag images + padded mask, one launch.
__global__ void prep_all(const float* __restrict__ qkv_w, const float* __restrict__ proj_w,
                         const float* __restrict__ fc1w, const float* __restrict__ fc2w,
                         const float* __restrict__ amask,
                         __half* __restrict__ w, float* __restrict__ msk)
{
    int i = blockIdx.x * 256 + threadIdx.x;
    if (i < 110592) {
        int k = i / 576, n = i % 576;
        w[OFF_QKVW + bimg_idx(k, n, 192)] = __float2half_rn(qkv_w[i]);
    } else if (i < 147456) {
        int j = i - 110592, k = j / 192, n = j % 192;
        w[OFF_PROJW + bimg_idx(k, n, 192)] = __float2half_rn(proj_w[j]);
    } else if (i < 294912) {
        int j = i - 147456, k = j / 768, n = j % 768;
        w[OFF_FC1W + bimg_idx(k, n, 192)] = __float2half_rn(fc1w[j]);
    } else if (i < 442368) {
        int j = i - 294912, k = j / 192, n = j % 192;
        w[OFF_FC2W + bimg_idx(k, n, 768)] = __float2half_rn(fc2w[j]);
    } else if (i < 442368 + 64 * 49 * 56) {
        int j = i - 442368;
        int win = j / 2744, rj = j % 2744, r = rj / 56, jj = rj % 56;
        msk[j] = (jj < 49) ? amask[win * 2401 + r * 49 + jj] : -1e9f;
    }
}

// LayerNorm over C=192, one warp per row; writes half A-frag image.
__global__ void ln_kernel(const float* __restrict__ x, const float* __restrict__ g,
                          const float* __restrict__ bta, __half* __restrict__ out,
                          int permute)
{
    int row  = blockIdx.x * 8 + threadIdx.y;
    int lane = threadIdx.x;
    int src  = permute ? win_row_to_token(row) : row;
    const float* xp = x + (size_t)src * CC;
    float2 v[3];
    float s = 0.f, s2 = 0.f;
#pragma unroll
    for (int i = 0; i < 3; i++) {
        v[i] = *(const float2*)&xp[i * 64 + lane * 2];
        s += v[i].x + v[i].y;
        s2 += v[i].x * v[i].x + v[i].y * v[i].y;
    }
#pragma unroll
    for (int o = 16; o; o >>= 1) {
        s  += __shfl_xor_sync(0xffffffffu, s, o);
        s2 += __shfl_xor_sync(0xffffffffu, s2, o);
    }
    float mu  = s * (1.f / 192.f);
    float var = s2 * (1.f / 192.f) - mu * mu;
    float inv = rsqrtf(var + 1e-5f);
#pragma unroll
    for (int i = 0; i < 3; i++) {
        int c = i * 64 + lane * 2;
        float2 gg = *(const float2*)&g[c];
        float2 bb = *(const float2*)&bta[c];
        float o0 = (v[i].x - mu) * inv * gg.x + bb.x;
        float o1 = (v[i].y - mu) * inv * gg.y + bb.y;
        *(__half2*)&out[aimg_idx(row, c, 192)] = __floats2half2_rn(o0, o1);
    }
}

// FP16 mma.sync GEMM: CTA 256x64, 8 warps (4m x 2n), warp tile 64x32.
// EPI: 0 bias -> half linear; 2 bias+GELU -> half A-image (K'=768);
//      3 bias+residual -> fp32 linear.
template<int EPI>
__global__ void __launch_bounds__(256, 2)
tgemm(const __half* __restrict__ Aimg, const __half* __restrict__ Bimg,
      const float* __restrict__ bias, void* __restrict__ CoutV,
      int Nn, int K, const float* __restrict__ resid)
{
    extern __shared__ __half dsh[];
    __half* Asm = dsh;                // [2][8192] halves = 32KB
    __half* Bsm = dsh + 2 * 8192;     // [2][2048] halves = 8KB

    const int tid  = threadIdx.x;
    const int warp = tid >> 5, lane = tid & 31;
    const int gid = lane >> 2, qid = lane & 3;
    const int wm = warp >> 1, wn = warp & 1;
    const int bm = blockIdx.y * 256, bn = blockIdx.x * 64;
    const int nk = K >> 5;

    float acc[4][4][4] = {};

    const uint32_t asmb = (uint32_t)__cvta_generic_to_shared(Asm);
    const uint32_t bsmb = asmb + 32768;
    const __half* Ab = Aimg + (size_t)blockIdx.y * nk * 8192;
    const __half* Bb = Bimg + (size_t)blockIdx.x * nk * 2048;

    auto issue = [&](int c) {
        int st = c & 1;
        const uint4* as = (const uint4*)(Ab + (size_t)c * 8192) + tid;
        uint32_t ad = asmb + (uint32_t)(st * 16384 + tid * 16);
#pragma unroll
        for (int p = 0; p < 4; p++)
            asm volatile("cp.async.cg.shared.global [%0], [%1], 16;"
                         :: "r"(ad + p * 4096), "l"(as + p * 256));
        const uint4* bs = (const uint4*)(Bb + (size_t)c * 2048) + tid;
        uint32_t bd = bsmb + (uint32_t)(st * 4096 + tid * 16);
        asm volatile("cp.async.cg.shared.global [%0], [%1], 16;"
                     :: "r"(bd), "l"(bs));
        asm volatile("cp.async.commit_group;" ::: "memory");
    };

    issue(0);
    for (int c = 0; c < nk; c++) {
        if (c + 1 < nk) {
            issue(c + 1);
            asm volatile("cp.async.wait_group 1;" ::: "memory");
        } else {
            asm volatile("cp.async.wait_group 0;" ::: "memory");
        }
        __syncthreads();

        const __half* ab = Asm + (c & 1) * 8192;
        const __half* bb = Bsm + (c & 1) * 2048;
#pragma unroll
        for (int ks = 0; ks < 2; ks++) {
            uint4 fa[4];
#pragma unroll
            for (int mt = 0; mt < 4; mt++)
                fa[mt] = *(const uint4*)&ab[((wm * 4 + mt) * 2 + ks) * 256 + lane * 8];
            uint4 fb0 = *(const uint4*)&bb[(ks * 4 + wn * 2 + 0) * 256 + lane * 8];
            uint4 fb1 = *(const uint4*)&bb[(ks * 4 + wn * 2 + 1) * 256 + lane * 8];
#pragma unroll
            for (int mt = 0; mt < 4; mt++) {
                mma16(acc[mt][0], fa[mt], fb0.x, fb0.y);
                mma16(acc[mt][1], fa[mt], fb0.z, fb0.w);
                mma16(acc[mt][2], fa[mt], fb1.x, fb1.y);
                mma16(acc[mt][3], fa[mt], fb1.z, fb1.w);
            }
        }
        __syncthreads();
    }

#pragma unroll
    for (int mt = 0; mt < 4; mt++) {
#pragma unroll
        for (int hf = 0; hf < 2; hf++) {
            int row = bm + wm * 64 + mt * 16 + gid + hf * 8;
#pragma unroll
            for (int nt = 0; nt < 4; nt++) {
                int col = bn + wn * 32 + nt * 8 + qid * 2;
                float v0 = acc[mt][nt][hf * 2 + 0] + bias[col];
                float v1 = acc[mt][nt][hf * 2 + 1] + bias[col + 1];
                if (EPI == 0) {
                    __half* O = (__half*)CoutV;
                    *(__half2*)&O[(size_t)row * Nn + col] = __floats2half2_rn(v0, v1);
                } else if (EPI == 2) {
                    v0 = 0.5f * v0 * (1.f + erff(v0 * 0.70710678118654752f));
                    v1 = 0.5f * v1 * (1.f + erff(v1 * 0.70710678118654752f));
                    __half* O = (__half*)CoutV;
                    *(__half2*)&O[aimg_idx(row, col, 768)] = __floats2half2_rn(v0, v1);
                } else {
                    float* O = (float*)CoutV;
                    float r0 = resid[(size_t)row * CC + col];
                    float r1 = resid[(size_t)row * CC + col + 1];
                    *(float2*)&O[(size_t)row * Nn + col] = make_float2(v0 + r0, v1 + r1);
                }
            }
        }
    }
}

// proj GEMM + un-window/un-shift + fused LN2.
// CTA 128x192 (full row), 6 warps (2m x 3n), warp tile 64x64.
// Writes xr (fp32 linear, token order) AND h = LN2(xr) (half A-image).
__global__ void __launch_bounds__(192, 2)
projln(const __half* __restrict__ Aimg, const __half* __restrict__ Bimg,
       const float* __restrict__ bias, float* __restrict__ xr,
       __half* __restrict__ hout,
       const float* __restrict__ n2g, const float* __restrict__ n2b)
{
    extern __shared__ __half dsh[];
    __half* Asm = dsh;                // [2][4096] halves = 16KB
    __half* Bsm = dsh + 2 * 4096;     // [2][6144] halves = 24KB
    float* redS = (float*)(dsh + 2 * 4096 + 2 * 6144);   // [3][128]
    float* redQ = redS + 3 * 128;                        // [3][128]

    const int tid  = threadIdx.x;
    const int warp = tid >> 5, lane = tid & 31;
    const int gid = lane >> 2, qid = lane & 3;
    const int wm = warp / 3, wn = warp % 3;
    const int bm = blockIdx.y * 128;
    const int nk = 6;   // K = 192

    float acc[4][8][4] = {};

    const uint32_t asmb = (uint32_t)__cvta_generic_to_shared(Asm);
    const uint32_t bsmb = asmb + 16384;
    const __half* Ab = Aimg + (size_t)(bm >> 8) * nk * 8192 + ((bm >> 7) & 1) * 4096;

    auto issue = [&](int c) {
        int st = c & 1;
        const uint4* as = (const uint4*)(Ab + (size_t)c * 8192);
        uint32_t ad = asmb + (uint32_t)(st * 8192);
#pragma unroll
        for (int p = 0; p < 3; p++) {
            int idx = tid + p * 192;
            if (p < 2 || idx < 512)
                asm volatile("cp.async.cg.shared.global [%0], [%1], 16;"
                             :: "r"(ad + idx * 16), "l"(as + idx));
        }
        uint32_t bd = bsmb + (uint32_t)(st * 12288);
#pragma unroll
        for (int p = 0; p < 4; p++) {
            int idx = tid + p * 192;          // 0..767 (3 x-blocks x 256 uint4)
            int xb = idx >> 8, off = idx & 255;
            const uint4* bs = (const uint4*)(Bimg + ((size_t)xb * nk + c) * 2048) + off;
            asm volatile("cp.async.cg.shared.global [%0], [%1], 16;"
                         :: "r"(bd + idx * 16), "l"(bs));
        }
        asm volatile("cp.async.commit_group;" ::: "memory");
    };

    issue(0);
    for (int c = 0; c < nk; c++) {
        if (c + 1 < nk) {
            issue(c + 1);
            asm volatile("cp.async.wait_group 1;" ::: "memory");
        } else {
            asm volatile("cp.async.wait_group 0;" ::: "memory");
        }
        __syncthreads();

        const __half* ab = Asm + (c & 1) * 4096;
        const __half* bb = Bsm + (c & 1) * 6144 + wn * 2048;
#pragma unroll
        for (int ks = 0; ks < 2; ks++) {
            uint4 fa[4];
#pragma unroll
            for (int mt = 0; mt < 4; mt++)
                fa[mt] = *(const uint4*)&ab[(((wm * 4 + mt) * 2) + ks) * 256 + lane * 8];
#pragma unroll
            for (int s = 0; s < 4; s++) {
                uint4 fb = *(const uint4*)&bb[(ks * 4 + s) * 256 + lane * 8];
#pragma unroll
                for (int mt = 0; mt < 4; mt++) {
                    mma16(acc[mt][s * 2],     fa[mt], fb.x, fb.y);
                    mma16(acc[mt][s * 2 + 1], fa[mt], fb.z, fb.w);
                }
            }
        }
        __syncthreads();
    }

    // Row-sum partials (quad shuffle over 64 cols, per wn), then combine.
#pragma unroll
    for (int mt = 0; mt < 4; mt++) {
#pragma unroll
        for (int hf = 0; hf < 2; hf++) {
            float s = 0.f, q2 = 0.f;
#pragma unroll
            for (int nt = 0; nt < 8; nt++) {
                int col = wn * 64 + nt * 8 + qid * 2;
                float v0 = acc[mt][nt][hf * 2 + 0] + bias[col];
                float v1 = acc[mt][nt][hf * 2 + 1] + bias[col + 1];
                s += v0 + v1;
                q2 += v0 * v0 + v1 * v1;
            }
            s  += __shfl_xor_sync(0xffffffffu, s, 1);
            s  += __shfl_xor_sync(0xffffffffu, s, 2);
            q2 += __shfl_xor_sync(0xffffffffu, q2, 1);
            q2 += __shfl_xor_sync(0xffffffffu, q2, 2);
            if (qid == 0) {
                int ridx = wm * 64 + mt * 16 + hf * 8 + gid;
                redS[wn * 128 + ridx] = s;
                redQ[wn * 128 + ridx] = q2;
            }
        }
    }
    __syncthreads();

#pragma unroll
    for (int mt = 0; mt < 4; mt++) {
#pragma unroll
        for (int hf = 0; hf < 2; hf++) {
            int ridx = wm * 64 + mt * 16 + hf * 8 + gid;
            int row  = bm + ridx;
            int orow = win_row_to_token(row);
            float S  = redS[ridx] + redS[128 + ridx] + redS[256 + ridx];
            float Q  = redQ[ridx] + redQ[128 + ridx] + redQ[256 + ridx];
            float mu = S * (1.f / 192.f);
            float var = Q * (1.f / 192.f) - mu * mu;
            float inv = rsqrtf(var + 1e-5f);
#pragma unroll
            for (int nt = 0; nt < 8; nt++) {
                int col = wn * 64 + nt * 8 + qid * 2;
                float v0 = acc[mt][nt][hf * 2 + 0] + bias[col];
                float v1 = acc[mt][nt][hf * 2 + 1] + bias[col + 1];
                *(float2*)&xr[(size_t)orow * CC + col] = make_float2(v0, v1);
                float2 gg = *(const float2*)&n2g[col];
                float2 bb = *(const float2*)&n2b[col];
                float h0 = (v0 - mu) * inv * gg.x + bb.x;
                float h1 = (v1 - mu) * inv * gg.y + bb.y;
                *(__half2*)&hout[aimg_idx(orow, col, 192)] = __floats2half2_rn(h0, h1);
            }
        }
    }
}

// FP16 tensor-core attention: one CTA per (window, head), 4 warps.
// Raw-half Q copy (scale folded into softmax), minimal zero-fill,
// register-resident P, pre-folded output indexing.
__global__ void __launch_bounds__(128)
attn_kernel(const __half* __restrict__ qkv, const float* __restrict__ mask2,
            __half* __restrict__ out)
{
    int win  = blockIdx.x / NHEAD;
    int head = blockIdx.x % NHEAD;
    __shared__ __half qa[2048];        // Q A-frag image: 4 m16 x 2 ks x 256
    __shared__ __half kt[56 * 40];     // K [j][d], stride 40
    __shared__ __half vt[32 * 72];     // V^T [d][j], stride 72, j padded to 64

    const int tid = threadIdx.x;
    const int warp = tid >> 5, lane = tid & 31;
    const int gid = lane >> 2, qid = lane & 3;
    const float scale = 0.17677669529663687f;

    // zero only the pad regions (read-but-not-written)
    {
        uint32_t* z = (uint32_t*)qa;          // tile m16=3: halves 1536..2048
        for (int t = tid; t < 256; t += 128) z[768 + t] = 0;
        z = (uint32_t*)kt;                    // rows 49..55: halves 1960..2240
        for (int t = tid; t < 140; t += 128) z[980 + t] = 0;
        // vt cols 48..63, rows 0..31 (col 48 re-written with real data below)
        for (int t = tid; t < 256; t += 128) {
            int r = t >> 3, cw = t & 7;
            ((uint32_t*)vt)[(r * 72 + 48) / 2 + cw] = 0;
        }
    }
    __syncthreads();

    const __half* base = qkv + (size_t)win * 49 * 576;
    for (int t = tid; t < 49 * 8; t += 128) {
        int r = t >> 3, c4 = (t & 7) * 4;
        uint2 qv = *(const uint2*)&base[r * 576 +       head * 32 + c4];
        uint2 kv = *(const uint2*)&base[r * 576 + 192 + head * 32 + c4];
        uint2 vv = *(const uint2*)&base[r * 576 + 384 + head * 32 + c4];
        // K natural [j][d]
        *(uint2*)&kt[r * 40 + c4] = kv;
        // V transpose [d][j]
        __half2 v0 = *reinterpret_cast<__half2*>(&vv.x);
        __half2 v1 = *reinterpret_cast<__half2*>(&vv.y);
        vt[(c4 + 0) * 72 + r] = __low2half(v0);
        vt[(c4 + 1) * 72 + r] = __high2half(v0);
        vt[(c4 + 2) * 72 + r] = __low2half(v1);
        vt[(c4 + 3) * 72 + r] = __high2half(v1);
        // Q A-frag image, raw half bits (no scale here)
        int m16 = r >> 4, rr = r & 15;
        int ks = c4 >> 4, kk = c4 & 15;
        int q0 = (kk & 7) >> 1;
        int reg = (kk >> 3) * 2 + (rr >> 3);
        int idx = (m16 * 2 + ks) * 256 + ((rr & 7) * 4 + q0) * 8 + reg * 2;
        *(uint32_t*)&qa[idx]     = qv.x;
        *(uint32_t*)&qa[idx + 8] = qv.y;
    }
    __syncthreads();

    float sacc[7][4] = {};
#pragma unroll
    for (int ks = 0; ks < 2; ks++) {
        uint4 fa = *(const uint4*)&qa[(warp * 2 + ks) * 256 + lane * 8];
#pragma unroll
        for (int nt = 0; nt < 7; nt++) {
            uint32_t b0 = *(const uint32_t*)&kt[(nt * 8 + gid) * 40 + ks * 16 + qid * 2];
            uint32_t b1 = *(const uint32_t*)&kt[(nt * 8 + gid) * 40 + ks * 16 + 8 + qid * 2];
            mma16(sacc[nt], fa, b0, b1);
        }
    }

    // In-register masked softmax (scale folded in); P kept in registers.
    const float* msk = mask2 + (size_t)(win & 63) * 2744;
    uint32_t ph[2][8];
    ph[0][7] = 0u; ph[1][7] = 0u;      // j 56..63 pad = 0
#pragma unroll
    for (int hf = 0; hf < 2; hf++) {
        int r = warp * 16 + hf * 8 + gid;
        bool ok = (r < 49);
        float v[14];
#pragma unroll
        for (int nt = 0; nt < 7; nt++) {
            float2 mk = ok ? *(const float2*)&msk[r * 56 + nt * 8 + qid * 2]
                           : make_float2(-1e9f, -1e9f);
            v[nt * 2]     = fmaf(sacc[nt][hf * 2],     scale, mk.x);
            v[nt * 2 + 1] = fmaf(sacc[nt][hf * 2 + 1], scale, mk.y);
        }
        float m = v[0];
#pragma unroll
        for (int i = 1; i < 14; i++) m = fmaxf(m, v[i]);
        m = fmaxf(m, __shfl_xor_sync(0xffffffffu, m, 1));
        m = fmaxf(m, __shfl_xor_sync(0xffffffffu, m, 2));
        float s = 0.f;
#pragma unroll
        for (int i = 0; i < 14; i++) { v[i] = __expf(v[i] - m); s += v[i]; }
        s += __shfl_xor_sync(0xffffffffu, s, 1);
        s += __shfl_xor_sync(0xffffffffu, s, 2);
        float inv = 1.f / s;
#pragma unroll
        for (int nt = 0; nt < 7; nt++)
            ph[hf][nt] = h2_as_u32(
                __floats2half2_rn(v[nt * 2] * inv, v[nt * 2 + 1] * inv));
    }

    // O = P V : A-fragments assembled from ph registers (lane-identity).
    float oacc[4][4] = {};
#pragma unroll
    for (int ks = 0; ks < 4; ks++) {
        uint4 fa = make_uint4(ph[0][2 * ks], ph[1][2 * ks],
                              ph[0][2 * ks + 1], ph[1][2 * ks + 1]);
#pragma unroll
        for (int nt = 0; nt < 4; nt++) {
            uint32_t b0 = *(const uint32_t*)&vt[(nt * 8 + gid) * 72 + ks * 16 + qid * 2];
            uint32_t b1 = *(const uint32_t*)&vt[(nt * 8 + gid) * 72 + ks * 16 + 8 + qid * 2];
            mma16(oacc[nt], fa, b0, b1);
        }
    }

    // Output with pre-folded A-image indexing:
    // aimg_idx(r, head*32+nt*8+qid*2, 192) = base(r) + (nt>>1)*256 + (nt&1)*4
    int i0 = warp * 16 + gid, i1 = warp * 16 + 8 + gid;
    if (i0 < 49) {
        int r = win * 49 + i0;
        size_t b = ((size_t)(r >> 8) * 6 + head) * 8192
                 + (size_t)((((r & 255) >> 4) * 512) + (r & 7) * 32 + qid * 8
                            + ((r >> 3) & 1) * 2);
#pragma unroll
        for (int nt = 0; nt < 4; nt++)
            *(__half2*)&out[b + (nt >> 1) * 256 + (nt & 1) * 4] =
                __floats2half2_rn(oacc[nt][0], oacc[nt][1]);
    }
    if (i1 < 49) {
        int r = win * 49 + i1;
        size_t b = ((size_t)(r >> 8) * 6 + head) * 8192
                 + (size_t)((((r & 255) >> 4) * 512) + (r & 7) * 32 + qid * 8
                            + ((r >> 3) & 1) * 2);
#pragma unroll
        for (int nt = 0; nt < 4; nt++)
            *(__half2*)&out[b + (nt >> 1) * 256 + (nt & 1) * 4] =
                __floats2half2_rn(oacc[nt][2], oacc[nt][3]);
    }
}

extern "C" void kernel_launch(void* const* d_in, const int* in_sizes, int n_in,
                              void* d_out, int out_size)
{
    const float* x      = (const float*)d_in[0];
    const float* qkv_w  = (const float*)d_in[1];
    const float* qkv_b  = (const float*)d_in[2];
    const float* proj_w = (const float*)d_in[3];
    const float* proj_b = (const float*)d_in[4];
    const float* n1g    = (const float*)d_in[5];
    const float* n1b    = (const float*)d_in[6];
    const float* n2g    = (const float*)d_in[7];
    const float* n2b    = (const float*)d_in[8];
    const float* fc1w   = (const float*)d_in[9];
    const float* fc1b   = (const float*)d_in[10];
    const float* fc2w   = (const float*)d_in[11];
    const float* fc2b   = (const float*)d_in[12];
    const float* amask  = (const float*)d_in[13];
    float* out = (float*)d_out;

    __half *xn, *qkv, *att, *h, *h1, *w;
    float *xr, *msk;
    cudaGetSymbolAddress((void**)&xn,  g_xn);
    cudaGetSymbolAddress((void**)&qkv, g_qkv);
    cudaGetSymbolAddress((void**)&att, g_att);
    cudaGetSymbolAddress((void**)&xr,  g_xr);
    cudaGetSymbolAddress((void**)&h,   g_h);
    cudaGetSymbolAddress((void**)&h1,  g_h1);
    cudaGetSymbolAddress((void**)&w,   g_w);
    cudaGetSymbolAddress((void**)&msk, g_msk);

    const int SMEM_GEMM = 40960;    // 32KB A + 8KB B
    const int SMEM_PROJ = 40960 + 3072;  // 16KB A + 24KB B + 3KB LN reduce
    cudaFuncSetAttribute(tgemm<0>, cudaFuncAttributeMaxDynamicSharedMemorySize, SMEM_GEMM);
    cudaFuncSetAttribute(tgemm<2>, cudaFuncAttributeMaxDynamicSharedMemorySize, SMEM_GEMM);
    cudaFuncSetAttribute(tgemm<3>, cudaFuncAttributeMaxDynamicSharedMemorySize, SMEM_GEMM);
    cudaFuncSetAttribute(projln,   cudaFuncAttributeMaxDynamicSharedMemorySize, SMEM_PROJ);

    // 0) build B fragment images + padded mask (one launch)
    prep_all<<<(442368 + 64 * 49 * 56 + 255) / 256, 256>>>(
        qkv_w, proj_w, fc1w, fc2w, amask, w, msk);

    dim3 lnb(32, 8);
    // 1) shift + window partition + LN1 -> A-image
    ln_kernel<<<TOK / 8, lnb>>>(x, n1g, n1b, xn, 1);
    // 2) QKV GEMM (100352,192)@(192,576) -> half linear qkv
    tgemm<0><<<dim3(9, 392), 256, SMEM_GEMM>>>(xn, w + OFF_QKVW, qkv_b, qkv, 576, 192, nullptr);
    // 3) windowed attention -> A-image
    attn_kernel<<<NWIN * NHEAD, 128>>>(qkv, msk, att);
    // 4) proj GEMM + un-window/un-shift + fused LN2 -> xr (fp32) and h (A-image)
    projln<<<dim3(1, 784), 192, SMEM_PROJ>>>(att, w + OFF_PROJW, proj_b, xr, h, n2g, n2b);
    // 5) fc1 + exact GELU -> A-image (K=768)
    tgemm<2><<<dim3(12, 392), 256, SMEM_GEMM>>>(h, w + OFF_FC1W, fc1b, h1, 768, 192, nullptr);
    // 6) fc2 + bias + residual -> fp32 out
    tgemm<3><<<dim3(3, 392), 256, SMEM_GEMM>>>(h1, w + OFF_FC2W, fc2b, out, 192, 768, xr);
}

// round 17
// speedup vs baseline: 1.1112x; 1.0118x over previous
#include <cuda_runtime.h>
#include <cuda_fp16.h>
#include <math.h>
#include <stdint.h>

#define TOK   100352          // B*H*W tokens
#define CC    192
#define NHEAD 6
#define HDIM  32
#define NWIN  2048            // B * 64 windows
#define HIDN  768

// Scratch (allocation-free rule: __device__ globals; zero-initialized at load,
// pad regions are never written so they stay zero across graph replays).
__device__ __half g_xn [TOK * CC];          // LN1 out, A-frag image
__device__ __half g_qa [NWIN * NHEAD * 2048]; // Q A-frag images per (win,head)
__device__ __half g_kt [NWIN * NHEAD * 2240]; // K [j][40] images (j pad 49..55 = 0)
__device__ __half g_vt [NWIN * NHEAD * 2304]; // V^T [d][72] images (j pad 49..63 = 0)
__device__ __half g_att[TOK * CC];          // attn out, A-frag image
__device__ float  g_xr [TOK * CC];          // residual branch, fp32 linear
__device__ __half g_h  [TOK * CC];          // LN2 out, A-frag image
__device__ __half g_h1 [TOK * HIDN];        // fc1+gelu out, A-frag image
__device__ __half g_w  [442368];            // B-frag images (qkv|proj|fc1|fc2)
__device__ float  g_msk[64 * 49 * 56];      // padded mask [win][r][j56], -1e9 pad

#define OFF_QKVW  0
#define OFF_PROJW 110592
#define OFF_FC1W  147456
#define OFF_FC2W  294912

__device__ __forceinline__ int win_row_to_token(int row) {
    int win = row / 49, n = row % 49;
    int b   = win >> 6, wij = win & 63;
    int wi  = wij >> 3, wj  = wij & 7;
    int hh  = wi * 7 + n / 7;
    int ww  = wj * 7 + n % 7;
    int h = hh + 3; if (h >= 56) h -= 56;
    int w = ww + 3; if (w >= 56) w -= 56;
    return b * 3136 + h * 56 + w;
}

__device__ __forceinline__ uint32_t h2_as_u32(__half2 v) {
    return *reinterpret_cast<uint32_t*>(&v);
}

// A-fragment image (half) index for (row, col) of an [*, K] activation (m16n8k16).
__device__ __forceinline__ size_t aimg_idx(int row, int col, int K) {
    int nk  = K >> 5;
    int mb  = row >> 8, m = row & 255;
    int ch  = col >> 5, kin = col & 31;
    int m16 = m >> 4, rr = m & 15;
    int gid = rr & 7, hr = rr >> 3;
    int ks  = kin >> 4, kk = kin & 15;
    int hi  = kk >> 3, q = (kk & 7) >> 1, e = kk & 1;
    int lane = gid * 4 + q;
    int reg  = hi * 2 + hr;
    return ((size_t)mb * nk + ch) * 8192
         + (size_t)((m16 * 2 + ks) * 256 + lane * 8 + reg * 2 + e);
}

// B-fragment image (half) index for weight element (k, n), K the k-dim.
__device__ __forceinline__ size_t bimg_idx(int k, int n, int K) {
    int nk = K >> 5;
    int bx = n >> 6, n64 = n & 63;
    int ch = k >> 5, kin = k & 31;
    int ks = kin >> 4, kk = kin & 15;
    int hi = kk >> 3, q = (kk & 7) >> 1, e = kk & 1;
    int sg = n64 >> 4, ntp = (n64 >> 3) & 1, g = n64 & 7;
    int lane = g * 4 + q;
    return ((size_t)bx * nk + ch) * 2048
         + (size_t)((ks * 4 + sg) * 256 + lane * 8 + ntp * 4 + hi * 2 + e);
}

__device__ __forceinline__ void mma16(float* c, uint4 a, uint32_t b0, uint32_t b1) {
    asm volatile(
        "mma.sync.aligned.m16n8k16.row.col.f32.f16.f16.f32 "
        "{%0,%1,%2,%3},{%4,%5,%6,%7},{%8,%9},{%0,%1,%2,%3};"
        : "+f"(c[0]), "+f"(c[1]), "+f"(c[2]), "+f"(c[3])
        : "r"(a.x), "r"(a.y), "r"(a.z), "r"(a.w), "r"(b0), "r"(b1));
}

// Combined prep: 4 weight B-frag images + padded mask, one launch.
__global__ void prep_all(const float* __restrict__ qkv_w, const float* __restrict__ proj_w,
                         const float* __restrict__ fc1w, const float* __restrict__ fc2w,
                         const float* __restrict__ amask,
                         __half* __restrict__ w, float* __restrict__ msk)
{
    int i = blockIdx.x * 256 + threadIdx.x;
    if (i < 110592) {
        int k = i / 576, n = i % 576;
        w[OFF_QKVW + bimg_idx(k, n, 192)] = __float2half_rn(qkv_w[i]);
    } else if (i < 147456) {
        int j = i - 110592, k = j / 192, n = j % 192;
        w[OFF_PROJW + bimg_idx(k, n, 192)] = __float2half_rn(proj_w[j]);
    } else if (i < 294912) {
        int j = i - 147456, k = j / 768, n = j % 768;
        w[OFF_FC1W + bimg_idx(k, n, 192)] = __float2half_rn(fc1w[j]);
    } else if (i < 442368) {
        int j = i - 294912, k = j / 192, n = j % 192;
        w[OFF_FC2W + bimg_idx(k, n, 768)] = __float2half_rn(fc2w[j]);
    } else if (i < 442368 + 64 * 49 * 56) {
        int j = i - 442368;
        int win = j / 2744, rj = j % 2744, r = rj / 56, jj = rj % 56;
        msk[j] = (jj < 49) ? amask[win * 2401 + r * 49 + jj] : -1e9f;
    }
}

// LayerNorm over C=192, one warp per row; writes half A-frag image.
__global__ void ln_kernel(const float* __restrict__ x, const float* __restrict__ g,
                          const float* __restrict__ bta, __half* __restrict__ out,
                          int permute)
{
    int row  = blockIdx.x * 8 + threadIdx.y;
    int lane = threadIdx.x;
    int src  = permute ? win_row_to_token(row) : row;
    const float* xp = x + (size_t)src * CC;
    float2 v[3];
    float s = 0.f, s2 = 0.f;
#pragma unroll
    for (int i = 0; i < 3; i++) {
        v[i] = *(const float2*)&xp[i * 64 + lane * 2];
        s += v[i].x + v[i].y;
        s2 += v[i].x * v[i].x + v[i].y * v[i].y;
    }
#pragma unroll
    for (int o = 16; o; o >>= 1) {
        s  += __shfl_xor_sync(0xffffffffu, s, o);
        s2 += __shfl_xor_sync(0xffffffffu, s2, o);
    }
    float mu  = s * (1.f / 192.f);
    float var = s2 * (1.f / 192.f) - mu * mu;
    float inv = rsqrtf(var + 1e-5f);
#pragma unroll
    for (int i = 0; i < 3; i++) {
        int c = i * 64 + lane * 2;
        float2 gg = *(const float2*)&g[c];
        float2 bb = *(const float2*)&bta[c];
        float o0 = (v[i].x - mu) * inv * gg.x + bb.x;
        float o1 = (v[i].y - mu) * inv * gg.y + bb.y;
        *(__half2*)&out[aimg_idx(row, c, 192)] = __floats2half2_rn(o0, o1);
    }
}

// ---- Shared GEMM mainloop (CTA 256x64, 8 warps 4m x 2n, warp 64x32) ----
struct GemmCtx {
    float acc[4][4][4];
    int tid, warp, lane, gid, qid, wm, wn, bm, bn;
};

template<typename EpiF>
__device__ __forceinline__ void gemm_main(const __half* Aimg, const __half* Bimg,
                                          int K, __half* Asm, __half* Bsm,
                                          GemmCtx& cx, EpiF epi)
{
    const int tid = cx.tid;
    const int nk = K >> 5;
    const uint32_t asmb = (uint32_t)__cvta_generic_to_shared(Asm);
    const uint32_t bsmb = asmb + 32768;
    const __half* Ab = Aimg + (size_t)blockIdx.y * nk * 8192;
    const __half* Bb = Bimg + (size_t)blockIdx.x * nk * 2048;

    auto issue = [&](int c) {
        int st = c & 1;
        const uint4* as = (const uint4*)(Ab + (size_t)c * 8192) + tid;
        uint32_t ad = asmb + (uint32_t)(st * 16384 + tid * 16);
#pragma unroll
        for (int p = 0; p < 4; p++)
            asm volatile("cp.async.cg.shared.global [%0], [%1], 16;"
                         :: "r"(ad + p * 4096), "l"(as + p * 256));
        const uint4* bs = (const uint4*)(Bb + (size_t)c * 2048) + tid;
        uint32_t bd = bsmb + (uint32_t)(st * 4096 + tid * 16);
        asm volatile("cp.async.cg.shared.global [%0], [%1], 16;"
                     :: "r"(bd), "l"(bs));
        asm volatile("cp.async.commit_group;" ::: "memory");
    };

    issue(0);
    for (int c = 0; c < nk; c++) {
        if (c + 1 < nk) {
            issue(c + 1);
            asm volatile("cp.async.wait_group 1;" ::: "memory");
        } else {
            asm volatile("cp.async.wait_group 0;" ::: "memory");
        }
        __syncthreads();

        const __half* ab = Asm + (c & 1) * 8192;
        const __half* bb = Bsm + (c & 1) * 2048;
#pragma unroll
        for (int ks = 0; ks < 2; ks++) {
            uint4 fa[4];
#pragma unroll
            for (int mt = 0; mt < 4; mt++)
                fa[mt] = *(const uint4*)&ab[((cx.wm * 4 + mt) * 2 + ks) * 256 + cx.lane * 8];
            uint4 fb0 = *(const uint4*)&bb[(ks * 4 + cx.wn * 2 + 0) * 256 + cx.lane * 8];
            uint4 fb1 = *(const uint4*)&bb[(ks * 4 + cx.wn * 2 + 1) * 256 + cx.lane * 8];
#pragma unroll
            for (int mt = 0; mt < 4; mt++) {
                mma16(cx.acc[mt][0], fa[mt], fb0.x, fb0.y);
                mma16(cx.acc[mt][1], fa[mt], fb0.z, fb0.w);
                mma16(cx.acc[mt][2], fa[mt], fb1.x, fb1.y);
                mma16(cx.acc[mt][3], fa[mt], fb1.z, fb1.w);
            }
        }
        __syncthreads();
    }
    epi(cx);
}

// Generic GEMM: EPI 2 bias+GELU -> half A-image (K'=768); 3 bias+residual -> fp32.
template<int EPI>
__global__ void __launch_bounds__(256, 2)
tgemm(const __half* __restrict__ Aimg, const __half* __restrict__ Bimg,
      const float* __restrict__ bias, void* __restrict__ CoutV,
      int Nn, int K, const float* __restrict__ resid)
{
    extern __shared__ __half dsh[];
    GemmCtx cx;
    cx.tid = threadIdx.x; cx.warp = cx.tid >> 5; cx.lane = cx.tid & 31;
    cx.gid = cx.lane >> 2; cx.qid = cx.lane & 3;
    cx.wm = cx.warp >> 1; cx.wn = cx.warp & 1;
    cx.bm = blockIdx.y * 256; cx.bn = blockIdx.x * 64;
#pragma unroll
    for (int a = 0; a < 4; a++)
#pragma unroll
        for (int b = 0; b < 4; b++)
#pragma unroll
            for (int c = 0; c < 4; c++) cx.acc[a][b][c] = 0.f;

    gemm_main(Aimg, Bimg, K, dsh, dsh + 2 * 8192, cx, [&](GemmCtx& x) {
#pragma unroll
        for (int mt = 0; mt < 4; mt++) {
#pragma unroll
            for (int hf = 0; hf < 2; hf++) {
                int row = x.bm + x.wm * 64 + mt * 16 + x.gid + hf * 8;
#pragma unroll
                for (int nt = 0; nt < 4; nt++) {
                    int col = x.bn + x.wn * 32 + nt * 8 + x.qid * 2;
                    float v0 = x.acc[mt][nt][hf * 2 + 0] + bias[col];
                    float v1 = x.acc[mt][nt][hf * 2 + 1] + bias[col + 1];
                    if (EPI == 2) {
                        v0 = 0.5f * v0 * (1.f + erff(v0 * 0.70710678118654752f));
                        v1 = 0.5f * v1 * (1.f + erff(v1 * 0.70710678118654752f));
                        __half* O = (__half*)CoutV;
                        *(__half2*)&O[aimg_idx(row, col, 768)] = __floats2half2_rn(v0, v1);
                    } else {
                        float* O = (float*)CoutV;
                        float r0 = resid[(size_t)row * CC + col];
                        float r1 = resid[(size_t)row * CC + col + 1];
                        *(float2*)&O[(size_t)row * Nn + col] = make_float2(v0 + r0, v1 + r1);
                    }
                }
            }
        }
    });
}

// QKV GEMM: writes attention-ready images. blocks 0-2 = Q (A-frag image),
// 3-5 = K ([j][40]), 6-8 = V^T ([d][72]).
__global__ void __launch_bounds__(256, 2)
qkvgemm(const __half* __restrict__ Aimg, const __half* __restrict__ Bimg,
        const float* __restrict__ bias,
        __half* __restrict__ qa, __half* __restrict__ kt, __half* __restrict__ vt)
{
    extern __shared__ __half dsh[];
    GemmCtx cx;
    cx.tid = threadIdx.x; cx.warp = cx.tid >> 5; cx.lane = cx.tid & 31;
    cx.gid = cx.lane >> 2; cx.qid = cx.lane & 3;
    cx.wm = cx.warp >> 1; cx.wn = cx.warp & 1;
    cx.bm = blockIdx.y * 256; cx.bn = blockIdx.x * 64;
#pragma unroll
    for (int a = 0; a < 4; a++)
#pragma unroll
        for (int b = 0; b < 4; b++)
#pragma unroll
            for (int c = 0; c < 4; c++) cx.acc[a][b][c] = 0.f;

    const int region = blockIdx.x / 3;                    // 0 q, 1 k, 2 v
    const int head = ((cx.bn % 192) >> 5) + cx.wn;        // constant per thread

    gemm_main(Aimg, Bimg, 192, dsh, dsh + 2 * 8192, cx, [&](GemmCtx& x) {
#pragma unroll
        for (int mt = 0; mt < 4; mt++) {
#pragma unroll
            for (int hf = 0; hf < 2; hf++) {
                int row = x.bm + x.wm * 64 + mt * 16 + x.gid + hf * 8;
                int win = row / 49, j = row - win * 49;
                size_t B = (size_t)(win * 6 + head);
                if (region == 0) {
                    int m16 = j >> 4, rr = j & 15, hr = rr >> 3;
                    size_t base = B * 2048
                        + (size_t)((m16 * 2) * 256 + ((rr & 7) * 4 + x.qid) * 8 + hr * 2);
#pragma unroll
                    for (int nt = 0; nt < 4; nt++) {
                        int col = x.bn + x.wn * 32 + nt * 8 + x.qid * 2;
                        float v0 = x.acc[mt][nt][hf * 2 + 0] + bias[col];
                        float v1 = x.acc[mt][nt][hf * 2 + 1] + bias[col + 1];
                        *(__half2*)&qa[base + (nt >> 1) * 256 + (nt & 1) * 4] =
                            __floats2half2_rn(v0, v1);
                    }
                } else if (region == 1) {
                    size_t base = B * 2240 + (size_t)(j * 40 + x.qid * 2);
#pragma unroll
                    for (int nt = 0; nt < 4; nt++) {
                        int col = x.bn + x.wn * 32 + nt * 8 + x.qid * 2;
                        float v0 = x.acc[mt][nt][hf * 2 + 0] + bias[col];
                        float v1 = x.acc[mt][nt][hf * 2 + 1] + bias[col + 1];
                        *(__half2*)&kt[base + nt * 8] = __floats2half2_rn(v0, v1);
                    }
                } else {
                    size_t base = B * 2304 + (size_t)j;
#pragma unroll
                    for (int nt = 0; nt < 4; nt++) {
                        int col = x.bn + x.wn * 32 + nt * 8 + x.qid * 2;
                        float v0 = x.acc[mt][nt][hf * 2 + 0] + bias[col];
                        float v1 = x.acc[mt][nt][hf * 2 + 1] + bias[col + 1];
                        int d = nt * 8 + x.qid * 2;
                        vt[base + (size_t)d * 72]       = __float2half_rn(v0);
                        vt[base + (size_t)(d + 1) * 72] = __float2half_rn(v1);
                    }
                }
            }
        }
    });
}

// proj GEMM + un-window/un-shift + fused LN2 (unchanged from round 15).
__global__ void __launch_bounds__(192, 2)
projln(const __half* __restrict__ Aimg, const __half* __restrict__ Bimg,
       const float* __restrict__ bias, float* __restrict__ xr,
       __half* __restrict__ hout,
       const float* __restrict__ n2g, const float* __restrict__ n2b)
{
    extern __shared__ __half dsh[];
    __half* Asm = dsh;                // [2][4096] halves = 16KB
    __half* Bsm = dsh + 2 * 4096;     // [2][6144] halves = 24KB
    float* redS = (float*)(dsh + 2 * 4096 + 2 * 6144);   // [3][128]
    float* redQ = redS + 3 * 128;                        // [3][128]

    const int tid  = threadIdx.x;
    const int warp = tid >> 5, lane = tid & 31;
    const int gid = lane >> 2, qid = lane & 3;
    const int wm = warp / 3, wn = warp % 3;
    const int bm = blockIdx.y * 128;
    const int nk = 6;   // K = 192

    float acc[4][8][4] = {};

    const uint32_t asmb = (uint32_t)__cvta_generic_to_shared(Asm);
    const uint32_t bsmb = asmb + 16384;
    const __half* Ab = Aimg + (size_t)(bm >> 8) * nk * 8192 + ((bm >> 7) & 1) * 4096;

    auto issue = [&](int c) {
        int st = c & 1;
        const uint4* as = (const uint4*)(Ab + (size_t)c * 8192);
        uint32_t ad = asmb + (uint32_t)(st * 8192);
#pragma unroll
        for (int p = 0; p < 3; p++) {
            int idx = tid + p * 192;
            if (p < 2 || idx < 512)
                asm volatile("cp.async.cg.shared.global [%0], [%1], 16;"
                             :: "r"(ad + idx * 16), "l"(as + idx));
        }
        uint32_t bd = bsmb + (uint32_t)(st * 12288);
#pragma unroll
        for (int p = 0; p < 4; p++) {
            int idx = tid + p * 192;
            int xb = idx >> 8, off = idx & 255;
            const uint4* bs = (const uint4*)(Bimg + ((size_t)xb * nk + c) * 2048) + off;
            asm volatile("cp.async.cg.shared.global [%0], [%1], 16;"
                         :: "r"(bd + idx * 16), "l"(bs));
        }
        asm volatile("cp.async.commit_group;" ::: "memory");
    };

    issue(0);
    for (int c = 0; c < nk; c++) {
        if (c + 1 < nk) {
            issue(c + 1);
            asm volatile("cp.async.wait_group 1;" ::: "memory");
        } else {
            asm volatile("cp.async.wait_group 0;" ::: "memory");
        }
        __syncthreads();

        const __half* ab = Asm + (c & 1) * 4096;
        const __half* bb = Bsm + (c & 1) * 6144 + wn * 2048;
#pragma unroll
        for (int ks = 0; ks < 2; ks++) {
            uint4 fa[4];
#pragma unroll
            for (int mt = 0; mt < 4; mt++)
                fa[mt] = *(const uint4*)&ab[(((wm * 4 + mt) * 2) + ks) * 256 + lane * 8];
#pragma unroll
            for (int s = 0; s < 4; s++) {
                uint4 fb = *(const uint4*)&bb[(ks * 4 + s) * 256 + lane * 8];
#pragma unroll
                for (int mt = 0; mt < 4; mt++) {
                    mma16(acc[mt][s * 2],     fa[mt], fb.x, fb.y);
                    mma16(acc[mt][s * 2 + 1], fa[mt], fb.z, fb.w);
                }
            }
        }
        __syncthreads();
    }

#pragma unroll
    for (int mt = 0; mt < 4; mt++) {
#pragma unroll
        for (int hf = 0; hf < 2; hf++) {
            float s = 0.f, q2 = 0.f;
#pragma unroll
            for (int nt = 0; nt < 8; nt++) {
                int col = wn * 64 + nt * 8 + qid * 2;
                float v0 = acc[mt][nt][hf * 2 + 0] + bias[col];
                float v1 = acc[mt][nt][hf * 2 + 1] + bias[col + 1];
                s += v0 + v1;
                q2 += v0 * v0 + v1 * v1;
            }
            s  += __shfl_xor_sync(0xffffffffu, s, 1);
            s  += __shfl_xor_sync(0xffffffffu, s, 2);
            q2 += __shfl_xor_sync(0xffffffffu, q2, 1);
            q2 += __shfl_xor_sync(0xffffffffu, q2, 2);
            if (qid == 0) {
                int ridx = wm * 64 + mt * 16 + hf * 8 + gid;
                redS[wn * 128 + ridx] = s;
                redQ[wn * 128 + ridx] = q2;
            }
        }
    }
    __syncthreads();

#pragma unroll
    for (int mt = 0; mt < 4; mt++) {
#pragma unroll
        for (int hf = 0; hf < 2; hf++) {
            int ridx = wm * 64 + mt * 16 + hf * 8 + gid;
            int row  = bm + ridx;
            int orow = win_row_to_token(row);
            float S  = redS[ridx] + redS[128 + ridx] + redS[256 + ridx];
            float Q  = redQ[ridx] + redQ[128 + ridx] + redQ[256 + ridx];
            float mu = S * (1.f / 192.f);
            float var = Q * (1.f / 192.f) - mu * mu;
            float inv = rsqrtf(var + 1e-5f);
#pragma unroll
            for (int nt = 0; nt < 8; nt++) {
                int col = wn * 64 + nt * 8 + qid * 2;
                float v0 = acc[mt][nt][hf * 2 + 0] + bias[col];
                float v1 = acc[mt][nt][hf * 2 + 1] + bias[col + 1];
                *(float2*)&xr[(size_t)orow * CC + col] = make_float2(v0, v1);
                float2 gg = *(const float2*)&n2g[col];
                float2 bb = *(const float2*)&n2b[col];
                float h0 = (v0 - mu) * inv * gg.x + bb.x;
                float h1 = (v1 - mu) * inv * gg.y + bb.y;
                *(__half2*)&hout[aimg_idx(orow, col, 192)] = __floats2half2_rn(h0, h1);
            }
        }
    }
}

// FP16 attention on pre-formatted images: Q A-frags straight from gmem,
// K/V contiguous uint4 smem copies, register softmax, pre-folded output.
__global__ void __launch_bounds__(128)
attn_kernel(const __half* __restrict__ qaimg, const __half* __restrict__ ktimg,
            const __half* __restrict__ vtimg, const float* __restrict__ mask2,
            __half* __restrict__ out)
{
    int win  = blockIdx.x / NHEAD;
    int head = blockIdx.x % NHEAD;
    __shared__ __half kt[2240];     // [j][40]
    __shared__ __half vt[2304];     // [d][72]

    const int tid = threadIdx.x;
    const int warp = tid >> 5, lane = tid & 31;
    const int gid = lane >> 2, qid = lane & 3;
    const float scale = 0.17677669529663687f;
    const size_t B = (size_t)(win * 6 + head);

    {
        const uint4* ks = (const uint4*)(ktimg + B * 2240);
        const uint4* vs = (const uint4*)(vtimg + B * 2304);
        uint4* kd = (uint4*)kt;
        uint4* vd = (uint4*)vt;
        for (int t = tid; t < 280; t += 128) kd[t] = ks[t];   // 2240 halves
        for (int t = tid; t < 288; t += 128) vd[t] = vs[t];   // 2304 halves
    }
    __syncthreads();

    // S = Q K^T, Q A-fragments direct from gmem image.
    const __half* qb = qaimg + B * 2048;
    float sacc[7][4] = {};
#pragma unroll
    for (int ks = 0; ks < 2; ks++) {
        uint4 fa = *(const uint4*)&qb[(warp * 2 + ks) * 256 + lane * 8];
#pragma unroll
        for (int nt = 0; nt < 7; nt++) {
            uint32_t b0 = *(const uint32_t*)&kt[(nt * 8 + gid) * 40 + ks * 16 + qid * 2];
            uint32_t b1 = *(const uint32_t*)&kt[(nt * 8 + gid) * 40 + ks * 16 + 8 + qid * 2];
            mma16(sacc[nt], fa, b0, b1);
        }
    }

    // In-register masked softmax (scale folded); P kept in registers.
    const float* msk = mask2 + (size_t)(win & 63) * 2744;
    uint32_t ph[2][8];
    ph[0][7] = 0u; ph[1][7] = 0u;
#pragma unroll
    for (int hf = 0; hf < 2; hf++) {
        int r = warp * 16 + hf * 8 + gid;
        bool ok = (r < 49);
        float v[14];
#pragma unroll
        for (int nt = 0; nt < 7; nt++) {
            float2 mk = ok ? *(const float2*)&msk[r * 56 + nt * 8 + qid * 2]
                           : make_float2(-1e9f, -1e9f);
            v[nt * 2]     = fmaf(sacc[nt][hf * 2],     scale, mk.x);
            v[nt * 2 + 1] = fmaf(sacc[nt][hf * 2 + 1], scale, mk.y);
        }
        float m = v[0];
#pragma unroll
        for (int i = 1; i < 14; i++) m = fmaxf(m, v[i]);
        m = fmaxf(m, __shfl_xor_sync(0xffffffffu, m, 1));
        m = fmaxf(m, __shfl_xor_sync(0xffffffffu, m, 2));
        float s = 0.f;
#pragma unroll
        for (int i = 0; i < 14; i++) { v[i] = __expf(v[i] - m); s += v[i]; }
        s += __shfl_xor_sync(0xffffffffu, s, 1);
        s += __shfl_xor_sync(0xffffffffu, s, 2);
        float inv = 1.f / s;
#pragma unroll
        for (int nt = 0; nt < 7; nt++)
            ph[hf][nt] = h2_as_u32(
                __floats2half2_rn(v[nt * 2] * inv, v[nt * 2 + 1] * inv));
    }

    // O = P V.
    float oacc[4][4] = {};
#pragma unroll
    for (int ks = 0; ks < 4; ks++) {
        uint4 fa = make_uint4(ph[0][2 * ks], ph[1][2 * ks],
                              ph[0][2 * ks + 1], ph[1][2 * ks + 1]);
#pragma unroll
        for (int nt = 0; nt < 4; nt++) {
            uint32_t b0 = *(const uint32_t*)&vt[(nt * 8 + gid) * 72 + ks * 16 + qid * 2];
            uint32_t b1 = *(const uint32_t*)&vt[(nt * 8 + gid) * 72 + ks * 16 + 8 + qid * 2];
            mma16(oacc[nt], fa, b0, b1);
        }
    }

    int i0 = warp * 16 + gid, i1 = warp * 16 + 8 + gid;
    if (i0 < 49) {
        int r = win * 49 + i0;
        size_t b = ((size_t)(r >> 8) * 6 + head) * 8192
                 + (size_t)((((r & 255) >> 4) * 512) + (r & 7) * 32 + qid * 8
                            + ((r >> 3) & 1) * 2);
#pragma unroll
        for (int nt = 0; nt < 4; nt++)
            *(__half2*)&out[b + (nt >> 1) * 256 + (nt & 1) * 4] =
                __floats2half2_rn(oacc[nt][0], oacc[nt][1]);
    }
    if (i1 < 49) {
        int r = win * 49 + i1;
        size_t b = ((size_t)(r >> 8) * 6 + head) * 8192
                 + (size_t)((((r & 255) >> 4) * 512) + (r & 7) * 32 + qid * 8
                            + ((r >> 3) & 1) * 2);
#pragma unroll
        for (int nt = 0; nt < 4; nt++)
            *(__half2*)&out[b + (nt >> 1) * 256 + (nt & 1) * 4] =
                __floats2half2_rn(oacc[nt][2], oacc[nt][3]);
    }
}

extern "C" void kernel_launch(void* const* d_in, const int* in_sizes, int n_in,
                              void* d_out, int out_size)
{
    const float* x      = (const float*)d_in[0];
    const float* qkv_w  = (const float*)d_in[1];
    const float* qkv_b  = (const float*)d_in[2];
    const float* proj_w = (const float*)d_in[3];
    const float* proj_b = (const float*)d_in[4];
    const float* n1g    = (const float*)d_in[5];
    const float* n1b    = (const float*)d_in[6];
    const float* n2g    = (const float*)d_in[7];
    const float* n2b    = (const float*)d_in[8];
    const float* fc1w   = (const float*)d_in[9];
    const float* fc1b   = (const float*)d_in[10];
    const float* fc2w   = (const float*)d_in[11];
    const float* fc2b   = (const float*)d_in[12];
    const float* amask  = (const float*)d_in[13];
    float* out = (float*)d_out;

    __half *xn, *qa, *kt, *vt, *att, *h, *h1, *w;
    float *xr, *msk;
    cudaGetSymbolAddress((void**)&xn,  g_xn);
    cudaGetSymbolAddress((void**)&qa,  g_qa);
    cudaGetSymbolAddress((void**)&kt,  g_kt);
    cudaGetSymbolAddress((void**)&vt,  g_vt);
    cudaGetSymbolAddress((void**)&att, g_att);
    cudaGetSymbolAddress((void**)&xr,  g_xr);
    cudaGetSymbolAddress((void**)&h,   g_h);
    cudaGetSymbolAddress((void**)&h1,  g_h1);
    cudaGetSymbolAddress((void**)&w,   g_w);
    cudaGetSymbolAddress((void**)&msk, g_msk);

    const int SMEM_GEMM = 40960;    // 32KB A + 8KB B
    const int SMEM_PROJ = 40960 + 3072;
    cudaFuncSetAttribute(qkvgemm,  cudaFuncAttributeMaxDynamicSharedMemorySize, SMEM_GEMM);
    cudaFuncSetAttribute(tgemm<2>, cudaFuncAttributeMaxDynamicSharedMemorySize, SMEM_GEMM);
    cudaFuncSetAttribute(tgemm<3>, cudaFuncAttributeMaxDynamicSharedMemorySize, SMEM_GEMM);
    cudaFuncSetAttribute(projln,   cudaFuncAttributeMaxDynamicSharedMemorySize, SMEM_PROJ);

    // 0) build B fragment images + padded mask (one launch)
    prep_all<<<(442368 + 64 * 49 * 56 + 255) / 256, 256>>>(
        qkv_w, proj_w, fc1w, fc2w, amask, w, msk);

    dim3 lnb(32, 8);
    // 1) shift + window partition + LN1 -> A-image
    ln_kernel<<<TOK / 8, lnb>>>(x, n1g, n1b, xn, 1);
    // 2) QKV GEMM -> per-(win,head) Q/K/V attention images
    qkvgemm<<<dim3(9, 392), 256, SMEM_GEMM>>>(xn, w + OFF_QKVW, qkv_b, qa, kt, vt);
    // 3) windowed attention -> A-image
    attn_kernel<<<NWIN * NHEAD, 128>>>(qa, kt, vt, msk, att);
    // 4) proj GEMM + un-window/un-shift + fused LN2 -> xr (fp32) and h (A-image)
    projln<<<dim3(1, 784), 192, SMEM_PROJ>>>(att, w + OFF_PROJW, proj_b, xr, h, n2g, n2b);
    // 5) fc1 + exact GELU -> A-image (K=768)
    tgemm<2><<<dim3(12, 392), 256, SMEM_GEMM>>>(h, w + OFF_FC1W, fc1b, h1, 768, 192, nullptr);
    // 6) fc2 + bias + residual -> fp32 out
    tgemm<3><<<dim3(3, 392), 256, SMEM_GEMM>>>(h1, w + OFF_FC2W, fc2b, out, 192, 768, xr);
}